// round 1
// baseline (speedup 1.0000x reference)
#include <cuda_runtime.h>

#define SIGMA_C 162.13039087945623f
#define MU_C    117.41975505778706f

__device__ __forceinline__ float fast_tanh(float x) {
    float y;
    asm("tanh.approx.f32 %0, %1;" : "=f"(y) : "f"(x));
    return y;
}

__global__ void __launch_bounds__(32) init_out_kernel(float* out, int B) {
    int i = threadIdx.x;
    if (i < B) out[i] = MU_C;
}

// Shared memory layout (floats), all offsets 16B-aligned:
//  W0T  [40][40] transposed fc0_w0          @ 0
//  B0   [40]                                @ 1600
//  W1T  [40][20] transposed fc0_w1          @ 1640
//  B1   [20]                                @ 2440
//  W2T  [20][20] transposed fc0_w2          @ 2460
//  B2   [20]                                @ 2860
//  W3T  [20][20] transposed fc1_w0          @ 2880
//  B3   [20]                                @ 3280
//  W4T  [20][12] transposed fc1_w1 (pad 12) @ 3300
//  B4   [12]    (pad)                       @ 3540
//  WF   [12]    fcf_w (pad)                 @ 3552
//  SC   [2]     w scalar, fcf_b             @ 3564
__global__ void __launch_bounds__(128) gnn_kernel(
    const float* __restrict__ feat,
    const float* __restrict__ nbc,
    const float* __restrict__ wts,
    const float* __restrict__ wscal,
    const float* __restrict__ w0, const float* __restrict__ b0,
    const float* __restrict__ w1, const float* __restrict__ b1,
    const float* __restrict__ w2, const float* __restrict__ b2,
    const float* __restrict__ w3, const float* __restrict__ b3,
    const float* __restrict__ w4, const float* __restrict__ b4,
    const float* __restrict__ wf, const float* __restrict__ bf,
    float* __restrict__ out, int N)
{
    constexpr int W0T = 0,    B0 = 1600, W1T = 1640, B1 = 2440;
    constexpr int W2T = 2460, B2 = 2860, W3T = 2880, B3 = 3280;
    constexpr int W4T = 3300, B4 = 3540, WF  = 3552, SC = 3564;
    __shared__ float sm[3568];
    __shared__ float red[128];

    const int tid = threadIdx.x;

    // Cooperative load + transpose of all weights into smem.
    for (int i = tid; i < 1600; i += 128) { int j = i / 40, k = i % 40; sm[W0T + k*40 + j] = w0[i]; }
    for (int i = tid; i < 40;   i += 128) sm[B0 + i] = b0[i];
    for (int i = tid; i < 800;  i += 128) { int j = i / 40, k = i % 40; sm[W1T + k*20 + j] = w1[i]; }
    for (int i = tid; i < 20;   i += 128) sm[B1 + i] = b1[i];
    for (int i = tid; i < 400;  i += 128) { int j = i / 20, k = i % 20; sm[W2T + k*20 + j] = w2[i]; }
    for (int i = tid; i < 20;   i += 128) sm[B2 + i] = b2[i];
    for (int i = tid; i < 400;  i += 128) { int j = i / 20, k = i % 20; sm[W3T + k*20 + j] = w3[i]; }
    for (int i = tid; i < 20;   i += 128) sm[B3 + i] = b3[i];
    for (int i = tid; i < 240;  i += 128) { int k = i / 12, j = i % 12; sm[W4T + i] = (j < 10) ? w4[j*20 + k] : 0.f; }
    for (int i = tid; i < 12;   i += 128) sm[B4 + i] = (i < 10) ? b4[i] : 0.f;
    for (int i = tid; i < 12;   i += 128) sm[WF + i] = (i < 10) ? wf[i] : 0.f;
    if (tid == 0) { sm[SC] = wscal[0]; sm[SC + 1] = bf[0]; }
    __syncthreads();

    const int n = blockIdx.x * 128 + tid;
    const int b = blockIdx.y;
    float contrib = 0.f;

    if (n < N) {
        const float w_ = sm[SC];
        const float c0a = nbc[n*6 + 0], c0b = nbc[n*6 + 1], c0c = nbc[n*6 + 2];
        const float c1a = nbc[n*6 + 3], c1b = nbc[n*6 + 4], c1c = nbc[n*6 + 5];
        const float nb0 = c0a + c0b + c0c;
        const float nb1 = c1a + c1b + c1c;
        const float nb0s = (nb0 < 1e-5f) ? 1e-5f : nb0;
        const float nb1s = (nb1 < 1e-5f) ? 1e-5f : nb1;
        const float h0 = (nb0 > 0.f) ? 1.f : 0.f;
        const float h1 = (nb1 > 0.f) ? 1.f : 0.f;
        const float inv0 = w_ / nb0s, inv1 = w_ / nb1s;
        float cs[7];
        cs[0] = 1.f - h0 * w_ - h1 * w_;
        cs[1] = c0a * inv0; cs[2] = c0b * inv0; cs[3] = c0c * inv0;
        cs[4] = c1a * inv1; cs[5] = c1b * inv1; cs[6] = c1c * inv1;

        const float4* fb = reinterpret_cast<const float4*>(feat) + ((size_t)b * N + n) * 70;

        float m[20];
        #pragma unroll
        for (int j = 0; j < 20; j++) m[j] = 0.f;

        #pragma unroll 1
        for (int s = 0; s < 7; s++) {
            const float4* xr = fb + s * 10;

            // ---- fc0 layer 0: 40 -> 40 ----
            float h[40];
            #pragma unroll
            for (int j = 0; j < 40; j++) h[j] = sm[B0 + j];
            #pragma unroll 2
            for (int kk = 0; kk < 10; kk++) {
                float4 xv = xr[kk];
                float xs4[4] = {xv.x, xv.y, xv.z, xv.w};
                #pragma unroll
                for (int u = 0; u < 4; u++) {
                    const float xk = xs4[u];
                    const int k = kk * 4 + u;
                    const float4* wrow = reinterpret_cast<const float4*>(&sm[W0T + k * 40]);
                    #pragma unroll
                    for (int j4 = 0; j4 < 10; j4++) {
                        float4 wv = wrow[j4];
                        h[j4*4 + 0] += wv.x * xk;
                        h[j4*4 + 1] += wv.y * xk;
                        h[j4*4 + 2] += wv.z * xk;
                        h[j4*4 + 3] += wv.w * xk;
                    }
                }
            }
            #pragma unroll
            for (int j = 0; j < 40; j++) h[j] = fast_tanh(h[j]);

            // ---- fc0 layer 1: 40 -> 20 ----
            float g[20];
            #pragma unroll
            for (int j = 0; j < 20; j++) g[j] = sm[B1 + j];
            #pragma unroll
            for (int k = 0; k < 40; k++) {
                const float xk = h[k];
                const float4* wrow = reinterpret_cast<const float4*>(&sm[W1T + k * 20]);
                #pragma unroll
                for (int j4 = 0; j4 < 5; j4++) {
                    float4 wv = wrow[j4];
                    g[j4*4 + 0] += wv.x * xk;
                    g[j4*4 + 1] += wv.y * xk;
                    g[j4*4 + 2] += wv.z * xk;
                    g[j4*4 + 3] += wv.w * xk;
                }
            }
            #pragma unroll
            for (int j = 0; j < 20; j++) g[j] = fast_tanh(g[j]);

            // ---- fc0 layer 2: 20 -> 20 ----
            float h2[20];
            #pragma unroll
            for (int j = 0; j < 20; j++) h2[j] = sm[B2 + j];
            #pragma unroll
            for (int k = 0; k < 20; k++) {
                const float xk = g[k];
                const float4* wrow = reinterpret_cast<const float4*>(&sm[W2T + k * 20]);
                #pragma unroll
                for (int j4 = 0; j4 < 5; j4++) {
                    float4 wv = wrow[j4];
                    h2[j4*4 + 0] += wv.x * xk;
                    h2[j4*4 + 1] += wv.y * xk;
                    h2[j4*4 + 2] += wv.z * xk;
                    h2[j4*4 + 3] += wv.w * xk;
                }
            }
            const float c = cs[s];
            #pragma unroll
            for (int j = 0; j < 20; j++) m[j] += c * fast_tanh(h2[j]);
        }

        // ---- fc1 layer 0: 20 -> 20 ----
        float p[20];
        #pragma unroll
        for (int j = 0; j < 20; j++) p[j] = sm[B3 + j];
        #pragma unroll
        for (int k = 0; k < 20; k++) {
            const float xk = m[k];
            const float4* wrow = reinterpret_cast<const float4*>(&sm[W3T + k * 20]);
            #pragma unroll
            for (int j4 = 0; j4 < 5; j4++) {
                float4 wv = wrow[j4];
                p[j4*4 + 0] += wv.x * xk;
                p[j4*4 + 1] += wv.y * xk;
                p[j4*4 + 2] += wv.z * xk;
                p[j4*4 + 3] += wv.w * xk;
            }
        }
        #pragma unroll
        for (int j = 0; j < 20; j++) p[j] = fast_tanh(p[j]);

        // ---- fc1 layer 1: 20 -> 10 (padded to 12) ----
        float q[12];
        #pragma unroll
        for (int j = 0; j < 12; j++) q[j] = sm[B4 + j];
        #pragma unroll
        for (int k = 0; k < 20; k++) {
            const float xk = p[k];
            const float4* wrow = reinterpret_cast<const float4*>(&sm[W4T + k * 12]);
            #pragma unroll
            for (int j4 = 0; j4 < 3; j4++) {
                float4 wv = wrow[j4];
                q[j4*4 + 0] += wv.x * xk;
                q[j4*4 + 1] += wv.y * xk;
                q[j4*4 + 2] += wv.z * xk;
                q[j4*4 + 3] += wv.w * xk;
            }
        }

        // ---- final head: 10 -> 1 ----
        float e = sm[SC + 1];
        #pragma unroll
        for (int j = 0; j < 12; j++) e += fast_tanh(q[j]) * sm[WF + j];

        contrib = wts[n] * e;
    }

    // Block reduction, one atomic per block.
    red[tid] = contrib;
    __syncthreads();
    #pragma unroll
    for (int o = 64; o > 0; o >>= 1) {
        if (tid < o) red[tid] += red[tid + o];
        __syncthreads();
    }
    if (tid == 0) atomicAdd(&out[b], SIGMA_C * red[0]);
}

extern "C" void kernel_launch(void* const* d_in, const int* in_sizes, int n_in,
                              void* d_out, int out_size)
{
    const float* feat  = (const float*)d_in[0];
    const float* nbc   = (const float*)d_in[1];
    const float* wts   = (const float*)d_in[2];
    const float* wscal = (const float*)d_in[3];
    const float* w0 = (const float*)d_in[4];
    const float* b0 = (const float*)d_in[5];
    const float* w1 = (const float*)d_in[6];
    const float* b1 = (const float*)d_in[7];
    const float* w2 = (const float*)d_in[8];
    const float* b2 = (const float*)d_in[9];
    const float* w3 = (const float*)d_in[10];
    const float* b3 = (const float*)d_in[11];
    const float* w4 = (const float*)d_in[12];
    const float* b4 = (const float*)d_in[13];
    const float* wf = (const float*)d_in[14];
    const float* bf = (const float*)d_in[15];
    float* out = (float*)d_out;

    const int N = in_sizes[2];          // weights has N elements
    const int B = out_size;             // output is (B,)

    init_out_kernel<<<1, 32>>>(out, B);
    dim3 grid((N + 127) / 128, B);
    gnn_kernel<<<grid, 128>>>(feat, nbc, wts, wscal,
                              w0, b0, w1, b1, w2, b2,
                              w3, b3, w4, b4, wf, bf,
                              out, N);
}

// round 3
// speedup vs baseline: 2.9945x; 2.9945x over previous
#include <cuda_runtime.h>
#include <cstdint>

#define SIGMA_C 162.13039087945623f
#define MU_C    117.41975505778706f

typedef unsigned long long u64;
typedef unsigned int u32;

__device__ __forceinline__ float fast_tanh(float x) {
    float y;
    asm("tanh.approx.f32 %0, %1;" : "=f"(y) : "f"(x));
    return y;
}
__device__ __forceinline__ u64 pk2(float x) {
    u64 r; asm("mov.b64 %0, {%1, %1};" : "=l"(r) : "f"(x)); return r;
}
__device__ __forceinline__ u64 pk(float a, float b) {
    u64 r; asm("mov.b64 %0, {%1, %2};" : "=l"(r) : "f"(a), "f"(b)); return r;
}
__device__ __forceinline__ void upk(u64 v, float& a, float& b) {
    asm("mov.b64 {%0, %1}, %2;" : "=f"(a), "=f"(b) : "l"(v));
}
__device__ __forceinline__ u64 ffma2(u64 a, u64 b, u64 c) {
    u64 d; asm("fma.rn.f32x2 %0, %1, %2, %3;" : "=l"(d) : "l"(a), "l"(b), "l"(c)); return d;
}

__global__ void __launch_bounds__(32) init_out_kernel(float* out, int B) {
    int i = threadIdx.x;
    if (i < B) out[i] = MU_C;
}

// float offsets in dynamic smem
#define W0T 0
#define B0  1600
#define W1T 1640
#define B1  2440
#define W2T 2460
#define B2  2860
#define W3T 2880
#define B3  3280
#define W4T 3300
#define B4  3540
#define WF  3552
#define SC  3564
#define XB  3584
#define XBSZ (128*44)
#define RED (XB + 2*XBSZ)
#define SMEM_FLOATS (RED + 128)
#define SMEM_BYTES (SMEM_FLOATS * 4)

__global__ void __launch_bounds__(128, 3) gnn_kernel(
    const float* __restrict__ feat,
    const float* __restrict__ nbc,
    const float* __restrict__ wts,
    const float* __restrict__ wscal,
    const float* __restrict__ w0, const float* __restrict__ b0,
    const float* __restrict__ w1, const float* __restrict__ b1,
    const float* __restrict__ w2, const float* __restrict__ b2,
    const float* __restrict__ w3, const float* __restrict__ b3,
    const float* __restrict__ w4, const float* __restrict__ b4,
    const float* __restrict__ wf, const float* __restrict__ bf,
    float* __restrict__ out, int N)
{
    extern __shared__ float sm[];
    const int tid = threadIdx.x;
    const int n0  = blockIdx.x * 128;
    const int b   = blockIdx.y;
    const int n   = n0 + tid;
    const bool valid = (n < N);
    const int nvalid = (N - n0 < 128) ? (N - n0) : 128;

    // features base for this (b, block): float4 rows of 70 quads each
    const float4* fb = reinterpret_cast<const float4*>(feat) + ((size_t)b * N + n0) * 70;

    // ---- stage s=0 via cp.async ----
    {
        #pragma unroll
        for (int it = 0; it < 10; it++) {
            int i = it * 128 + tid;
            int row = i / 10, q = i % 10;
            if (row < nvalid) {
                u32 dst = (u32)__cvta_generic_to_shared(&sm[XB + row * 44 + q * 4]);
                const float4* src = fb + row * 70 + q;   // s=0
                asm volatile("cp.async.ca.shared.global [%0], [%1], 16;" :: "r"(dst), "l"(src));
            }
        }
        asm volatile("cp.async.commit_group;");
    }

    // ---- cooperative weight load + transpose ----
    for (int i = tid; i < 1600; i += 128) { int j = i / 40, k = i % 40; sm[W0T + k*40 + j] = w0[i]; }
    for (int i = tid; i < 40;   i += 128) sm[B0 + i] = b0[i];
    for (int i = tid; i < 800;  i += 128) { int j = i / 40, k = i % 40; sm[W1T + k*20 + j] = w1[i]; }
    for (int i = tid; i < 20;   i += 128) sm[B1 + i] = b1[i];
    for (int i = tid; i < 400;  i += 128) { int j = i / 20, k = i % 20; sm[W2T + k*20 + j] = w2[i]; }
    for (int i = tid; i < 20;   i += 128) sm[B2 + i] = b2[i];
    for (int i = tid; i < 400;  i += 128) { int j = i / 20, k = i % 20; sm[W3T + k*20 + j] = w3[i]; }
    for (int i = tid; i < 20;   i += 128) sm[B3 + i] = b3[i];
    for (int i = tid; i < 240;  i += 128) { int k = i / 12, j = i % 12; sm[W4T + i] = (j < 10) ? w4[j*20 + k] : 0.f; }
    for (int i = tid; i < 12;   i += 128) sm[B4 + i] = (i < 10) ? b4[i] : 0.f;
    for (int i = tid; i < 12;   i += 128) sm[WF + i] = (i < 10) ? wf[i] : 0.f;
    if (tid == 0) { sm[SC] = wscal[0]; sm[SC + 1] = bf[0]; }

    // ---- per-node message-pass coefficients + node weight ----
    float cs[7];
    float wt = 0.f;
    if (valid) {
        wt = wts[n];
        float c0a = nbc[n*6+0], c0b = nbc[n*6+1], c0c = nbc[n*6+2];
        float c1a = nbc[n*6+3], c1b = nbc[n*6+4], c1c = nbc[n*6+5];
        float w_ = wscal[0];
        float nb0 = c0a + c0b + c0c, nb1 = c1a + c1b + c1c;
        float nb0s = (nb0 < 1e-5f) ? 1e-5f : nb0;
        float nb1s = (nb1 < 1e-5f) ? 1e-5f : nb1;
        float h0 = (nb0 > 0.f) ? 1.f : 0.f;
        float h1 = (nb1 > 0.f) ? 1.f : 0.f;
        float inv0 = w_ / nb0s, inv1 = w_ / nb1s;
        cs[0] = 1.f - h0 * w_ - h1 * w_;
        cs[1] = c0a * inv0; cs[2] = c0b * inv0; cs[3] = c0c * inv0;
        cs[4] = c1a * inv1; cs[5] = c1b * inv1; cs[6] = c1c * inv1;
    }

    u64 m[10];
    #pragma unroll
    for (int j = 0; j < 10; j++) m[j] = 0ull;

    #pragma unroll 1
    for (int s = 0; s < 7; s++) {
        // prefetch next stage, wait for current
        if (s < 6) {
            int nb = (s + 1) & 1;
            #pragma unroll
            for (int it = 0; it < 10; it++) {
                int i = it * 128 + tid;
                int row = i / 10, q = i % 10;
                if (row < nvalid) {
                    u32 dst = (u32)__cvta_generic_to_shared(&sm[XB + nb*XBSZ + row * 44 + q * 4]);
                    const float4* src = fb + row * 70 + (s + 1) * 10 + q;
                    asm volatile("cp.async.ca.shared.global [%0], [%1], 16;" :: "r"(dst), "l"(src));
                }
            }
            asm volatile("cp.async.commit_group;");
            asm volatile("cp.async.wait_group 1;");
        } else {
            asm volatile("cp.async.wait_group 0;");
        }
        __syncthreads();

        if (valid) {
            const float* xr = &sm[XB + (s & 1) * XBSZ + tid * 44];

            // ---- fc0 layer 0: 40 -> 40 (f32x2) ----
            u64 h[20];
            const u64* bp0 = (const u64*)&sm[B0];
            #pragma unroll
            for (int j = 0; j < 20; j++) h[j] = bp0[j];
            #pragma unroll
            for (int kk = 0; kk < 10; kk++) {
                float4 xv = *(const float4*)&xr[kk * 4];
                float xs4[4] = {xv.x, xv.y, xv.z, xv.w};
                #pragma unroll
                for (int u = 0; u < 4; u++) {
                    u64 xx = pk2(xs4[u]);
                    const ulonglong2* wr = (const ulonglong2*)&sm[W0T + (kk*4 + u) * 40];
                    #pragma unroll
                    for (int j2 = 0; j2 < 10; j2++) {
                        ulonglong2 wv = wr[j2];
                        h[2*j2+0] = ffma2(xx, wv.x, h[2*j2+0]);
                        h[2*j2+1] = ffma2(xx, wv.y, h[2*j2+1]);
                    }
                }
            }
            float ht[40];
            #pragma unroll
            for (int j = 0; j < 20; j++) {
                float a, c; upk(h[j], a, c);
                ht[2*j+0] = fast_tanh(a);
                ht[2*j+1] = fast_tanh(c);
            }

            // ---- fc0 layer 1: 40 -> 20 ----
            u64 g[10];
            const u64* bp1 = (const u64*)&sm[B1];
            #pragma unroll
            for (int j = 0; j < 10; j++) g[j] = bp1[j];
            #pragma unroll
            for (int k = 0; k < 40; k++) {
                u64 xx = pk2(ht[k]);
                const ulonglong2* wr = (const ulonglong2*)&sm[W1T + k * 20];
                #pragma unroll
                for (int j2 = 0; j2 < 5; j2++) {
                    ulonglong2 wv = wr[j2];
                    g[2*j2+0] = ffma2(xx, wv.x, g[2*j2+0]);
                    g[2*j2+1] = ffma2(xx, wv.y, g[2*j2+1]);
                }
            }
            float gt[20];
            #pragma unroll
            for (int j = 0; j < 10; j++) {
                float a, c; upk(g[j], a, c);
                gt[2*j+0] = fast_tanh(a);
                gt[2*j+1] = fast_tanh(c);
            }

            // ---- fc0 layer 2: 20 -> 20 ----
            u64 t2[10];
            const u64* bp2 = (const u64*)&sm[B2];
            #pragma unroll
            for (int j = 0; j < 10; j++) t2[j] = bp2[j];
            #pragma unroll
            for (int k = 0; k < 20; k++) {
                u64 xx = pk2(gt[k]);
                const ulonglong2* wr = (const ulonglong2*)&sm[W2T + k * 20];
                #pragma unroll
                for (int j2 = 0; j2 < 5; j2++) {
                    ulonglong2 wv = wr[j2];
                    t2[2*j2+0] = ffma2(xx, wv.x, t2[2*j2+0]);
                    t2[2*j2+1] = ffma2(xx, wv.y, t2[2*j2+1]);
                }
            }
            // ---- message accumulate: m += cs[s] * tanh(t2) ----
            u64 cx = pk2(cs[s]);
            #pragma unroll
            for (int j = 0; j < 10; j++) {
                float a, c; upk(t2[j], a, c);
                m[j] = ffma2(cx, pk(fast_tanh(a), fast_tanh(c)), m[j]);
            }
        }
        __syncthreads();
    }

    float contrib = 0.f;
    if (valid) {
        float mt[20];
        #pragma unroll
        for (int j = 0; j < 10; j++) upk(m[j], mt[2*j+0], mt[2*j+1]);

        // ---- fc1 layer 0: 20 -> 20 ----
        u64 p[10];
        const u64* bp3 = (const u64*)&sm[B3];
        #pragma unroll
        for (int j = 0; j < 10; j++) p[j] = bp3[j];
        #pragma unroll
        for (int k = 0; k < 20; k++) {
            u64 xx = pk2(mt[k]);
            const ulonglong2* wr = (const ulonglong2*)&sm[W3T + k * 20];
            #pragma unroll
            for (int j2 = 0; j2 < 5; j2++) {
                ulonglong2 wv = wr[j2];
                p[2*j2+0] = ffma2(xx, wv.x, p[2*j2+0]);
                p[2*j2+1] = ffma2(xx, wv.y, p[2*j2+1]);
            }
        }
        float pt[20];
        #pragma unroll
        for (int j = 0; j < 10; j++) {
            float a, c; upk(p[j], a, c);
            pt[2*j+0] = fast_tanh(a);
            pt[2*j+1] = fast_tanh(c);
        }

        // ---- fc1 layer 1: 20 -> 10 (padded to 12) ----
        u64 q[6];
        const u64* bp4 = (const u64*)&sm[B4];
        #pragma unroll
        for (int j = 0; j < 6; j++) q[j] = bp4[j];
        #pragma unroll
        for (int k = 0; k < 20; k++) {
            u64 xx = pk2(pt[k]);
            const ulonglong2* wr = (const ulonglong2*)&sm[W4T + k * 12];
            #pragma unroll
            for (int j2 = 0; j2 < 3; j2++) {
                ulonglong2 wv = wr[j2];
                q[2*j2+0] = ffma2(xx, wv.x, q[2*j2+0]);
                q[2*j2+1] = ffma2(xx, wv.y, q[2*j2+1]);
            }
        }

        // ---- head: 10 -> 1 ---- (padded lanes have wf=0)
        float e = sm[SC + 1];
        #pragma unroll
        for (int j = 0; j < 6; j++) {
            float a, c; upk(q[j], a, c);
            e += fast_tanh(a) * sm[WF + 2*j + 0];
            e += fast_tanh(c) * sm[WF + 2*j + 1];
        }
        contrib = wt * e;
    }

    // ---- block reduce + one atomic ----
    sm[RED + tid] = contrib;
    __syncthreads();
    #pragma unroll
    for (int o = 64; o > 0; o >>= 1) {
        if (tid < o) sm[RED + tid] += sm[RED + tid + o];
        __syncthreads();
    }
    if (tid == 0) atomicAdd(&out[b], SIGMA_C * sm[RED]);
}

extern "C" void kernel_launch(void* const* d_in, const int* in_sizes, int n_in,
                              void* d_out, int out_size)
{
    const float* feat  = (const float*)d_in[0];
    const float* nbc   = (const float*)d_in[1];
    const float* wts   = (const float*)d_in[2];
    const float* wscal = (const float*)d_in[3];
    const float* w0 = (const float*)d_in[4];
    const float* b0 = (const float*)d_in[5];
    const float* w1 = (const float*)d_in[6];
    const float* b1 = (const float*)d_in[7];
    const float* w2 = (const float*)d_in[8];
    const float* b2 = (const float*)d_in[9];
    const float* w3 = (const float*)d_in[10];
    const float* b3 = (const float*)d_in[11];
    const float* w4 = (const float*)d_in[12];
    const float* b4 = (const float*)d_in[13];
    const float* wf = (const float*)d_in[14];
    const float* bf = (const float*)d_in[15];
    float* out = (float*)d_out;

    const int N = in_sizes[2];
    const int B = out_size;

    // Idempotent, capture-safe attribute set.
    cudaFuncSetAttribute(gnn_kernel, cudaFuncAttributeMaxDynamicSharedMemorySize, SMEM_BYTES);

    init_out_kernel<<<1, 32>>>(out, B);
    dim3 grid((N + 127) / 128, B);
    gnn_kernel<<<grid, 128, SMEM_BYTES>>>(feat, nbc, wts, wscal,
                                          w0, b0, w1, b1, w2, b2,
                                          w3, b3, w4, b4, wf, bf,
                                          out, N);
}

// round 4
// speedup vs baseline: 4.2195x; 1.4091x over previous
#include <cuda_runtime.h>
#include <cstdint>

#define SIGMA_C 162.13039087945623f
#define MU_C    117.41975505778706f

typedef unsigned long long u64;
typedef unsigned int u32;

__device__ __forceinline__ float fast_tanh(float x) {
    float y;
    asm("tanh.approx.f32 %0, %1;" : "=f"(y) : "f"(x));
    return y;
}
__device__ __forceinline__ u64 pk2(float x) {
    u64 r; asm("mov.b64 %0, {%1, %1};" : "=l"(r) : "f"(x)); return r;
}
__device__ __forceinline__ u64 pk(float a, float b) {
    u64 r; asm("mov.b64 %0, {%1, %2};" : "=l"(r) : "f"(a), "f"(b)); return r;
}
__device__ __forceinline__ void upk(u64 v, float& a, float& b) {
    asm("mov.b64 {%0, %1}, %2;" : "=f"(a), "=f"(b) : "l"(v));
}
__device__ __forceinline__ u64 ffma2(u64 a, u64 b, u64 c) {
    u64 d; asm("fma.rn.f32x2 %0, %1, %2, %3;" : "=l"(d) : "l"(a), "l"(b), "l"(c)); return d;
}

__global__ void __launch_bounds__(32) init_out_kernel(float* out, int B) {
    int i = threadIdx.x;
    if (i < B) out[i] = MU_C;
}

// float offsets in dynamic smem
#define W0T 0
#define B0  1600
#define W1T 1640
#define B1  2440
#define W2T 2460
#define B2  2860
#define W3T 2880
#define B3  3280
#define W4T 3300
#define B4  3540
#define WF  3552
#define SC  3564
#define XB  3584
#define XBSZ (128*44)
#define RED (XB + 4*XBSZ)
#define SMEM_FLOATS (RED + 128)
#define SMEM_BYTES (SMEM_FLOATS * 4)

// Process TWO s-columns sharing every weight LDS. Accumulates c0*tanh(out0)
// + c1*tanh(out1) into m[10] (f32x2 packed pairs of the 20 message dims).
__device__ __forceinline__ void compute_pair(
    const float* __restrict__ sm,
    const float* __restrict__ xr0, const float* __restrict__ xr1,
    float c0, float c1, u64* __restrict__ m)
{
    // ---- fc0 layer 0: 40 -> 40 ----
    u64 h0[20], h1[20];
    const u64* bp0 = (const u64*)&sm[B0];
    #pragma unroll
    for (int j = 0; j < 20; j++) { h0[j] = bp0[j]; h1[j] = bp0[j]; }
    #pragma unroll
    for (int kk = 0; kk < 10; kk++) {
        float4 xa = *(const float4*)&xr0[kk * 4];
        float4 xb = *(const float4*)&xr1[kk * 4];
        float xa4[4] = {xa.x, xa.y, xa.z, xa.w};
        float xb4[4] = {xb.x, xb.y, xb.z, xb.w};
        #pragma unroll
        for (int u = 0; u < 4; u++) {
            u64 xxa = pk2(xa4[u]);
            u64 xxb = pk2(xb4[u]);
            const ulonglong2* wr = (const ulonglong2*)&sm[W0T + (kk*4 + u) * 40];
            #pragma unroll
            for (int j2 = 0; j2 < 10; j2++) {
                ulonglong2 wv = wr[j2];
                h0[2*j2+0] = ffma2(xxa, wv.x, h0[2*j2+0]);
                h0[2*j2+1] = ffma2(xxa, wv.y, h0[2*j2+1]);
                h1[2*j2+0] = ffma2(xxb, wv.x, h1[2*j2+0]);
                h1[2*j2+1] = ffma2(xxb, wv.y, h1[2*j2+1]);
            }
        }
    }
    float ht0[40], ht1[40];
    #pragma unroll
    for (int j = 0; j < 20; j++) {
        float a, c;
        upk(h0[j], a, c); ht0[2*j+0] = fast_tanh(a); ht0[2*j+1] = fast_tanh(c);
        upk(h1[j], a, c); ht1[2*j+0] = fast_tanh(a); ht1[2*j+1] = fast_tanh(c);
    }

    // ---- fc0 layer 1: 40 -> 20 ----
    u64 g0[10], g1[10];
    const u64* bp1 = (const u64*)&sm[B1];
    #pragma unroll
    for (int j = 0; j < 10; j++) { g0[j] = bp1[j]; g1[j] = bp1[j]; }
    #pragma unroll
    for (int k = 0; k < 40; k++) {
        u64 xxa = pk2(ht0[k]);
        u64 xxb = pk2(ht1[k]);
        const ulonglong2* wr = (const ulonglong2*)&sm[W1T + k * 20];
        #pragma unroll
        for (int j2 = 0; j2 < 5; j2++) {
            ulonglong2 wv = wr[j2];
            g0[2*j2+0] = ffma2(xxa, wv.x, g0[2*j2+0]);
            g0[2*j2+1] = ffma2(xxa, wv.y, g0[2*j2+1]);
            g1[2*j2+0] = ffma2(xxb, wv.x, g1[2*j2+0]);
            g1[2*j2+1] = ffma2(xxb, wv.y, g1[2*j2+1]);
        }
    }
    float gt0[20], gt1[20];
    #pragma unroll
    for (int j = 0; j < 10; j++) {
        float a, c;
        upk(g0[j], a, c); gt0[2*j+0] = fast_tanh(a); gt0[2*j+1] = fast_tanh(c);
        upk(g1[j], a, c); gt1[2*j+0] = fast_tanh(a); gt1[2*j+1] = fast_tanh(c);
    }

    // ---- fc0 layer 2: 20 -> 20 ----
    u64 t0[10], t1[10];
    const u64* bp2 = (const u64*)&sm[B2];
    #pragma unroll
    for (int j = 0; j < 10; j++) { t0[j] = bp2[j]; t1[j] = bp2[j]; }
    #pragma unroll
    for (int k = 0; k < 20; k++) {
        u64 xxa = pk2(gt0[k]);
        u64 xxb = pk2(gt1[k]);
        const ulonglong2* wr = (const ulonglong2*)&sm[W2T + k * 20];
        #pragma unroll
        for (int j2 = 0; j2 < 5; j2++) {
            ulonglong2 wv = wr[j2];
            t0[2*j2+0] = ffma2(xxa, wv.x, t0[2*j2+0]);
            t0[2*j2+1] = ffma2(xxa, wv.y, t0[2*j2+1]);
            t1[2*j2+0] = ffma2(xxb, wv.x, t1[2*j2+0]);
            t1[2*j2+1] = ffma2(xxb, wv.y, t1[2*j2+1]);
        }
    }
    // ---- message accumulate ----
    u64 cx0 = pk2(c0), cx1 = pk2(c1);
    #pragma unroll
    for (int j = 0; j < 10; j++) {
        float a, c;
        upk(t0[j], a, c);
        m[j] = ffma2(cx0, pk(fast_tanh(a), fast_tanh(c)), m[j]);
        upk(t1[j], a, c);
        m[j] = ffma2(cx1, pk(fast_tanh(a), fast_tanh(c)), m[j]);
    }
}

__global__ void __launch_bounds__(128, 2) gnn_kernel(
    const float* __restrict__ feat,
    const float* __restrict__ nbc,
    const float* __restrict__ wts,
    const float* __restrict__ wscal,
    const float* __restrict__ w0, const float* __restrict__ b0,
    const float* __restrict__ w1, const float* __restrict__ b1,
    const float* __restrict__ w2, const float* __restrict__ b2,
    const float* __restrict__ w3, const float* __restrict__ b3,
    const float* __restrict__ w4, const float* __restrict__ b4,
    const float* __restrict__ wf, const float* __restrict__ bf,
    float* __restrict__ out, int N)
{
    extern __shared__ float sm[];
    const int tid = threadIdx.x;
    const int n0  = blockIdx.x * 128;
    const int b   = blockIdx.y;
    const int n   = n0 + tid;
    const bool valid = (n < N);
    const int nvalid = (N - n0 < 128) ? (N - n0) : 128;

    const float4* fb = reinterpret_cast<const float4*>(feat) + ((size_t)b * N + n0) * 70;

    // Stage s-column `sidx` into x slot `slot` (rows padded to 44 floats).
    #define STAGE(slot, sidx)                                                          \
        {                                                                              \
            _Pragma("unroll")                                                          \
            for (int it = 0; it < 10; it++) {                                          \
                int i = it * 128 + tid;                                                \
                int row = i / 10, q = i % 10;                                          \
                if (row < nvalid) {                                                    \
                    u32 dst = (u32)__cvta_generic_to_shared(                           \
                        &sm[XB + (slot)*XBSZ + row * 44 + q * 4]);                     \
                    const float4* src = fb + row * 70 + (sidx) * 10 + q;               \
                    asm volatile("cp.async.ca.shared.global [%0], [%1], 16;"           \
                                 :: "r"(dst), "l"(src));                               \
                }                                                                      \
            }                                                                          \
        }

    // Preload pairs (s0,s1) and (s2,s3) as two commit groups.
    STAGE(0, 0); STAGE(1, 1);
    asm volatile("cp.async.commit_group;");
    STAGE(2, 2); STAGE(3, 3);
    asm volatile("cp.async.commit_group;");

    // ---- cooperative weight load + transpose (overlaps with cp.async) ----
    for (int i = tid; i < 1600; i += 128) { int j = i / 40, k = i % 40; sm[W0T + k*40 + j] = w0[i]; }
    for (int i = tid; i < 40;   i += 128) sm[B0 + i] = b0[i];
    for (int i = tid; i < 800;  i += 128) { int j = i / 40, k = i % 40; sm[W1T + k*20 + j] = w1[i]; }
    for (int i = tid; i < 20;   i += 128) sm[B1 + i] = b1[i];
    for (int i = tid; i < 400;  i += 128) { int j = i / 20, k = i % 20; sm[W2T + k*20 + j] = w2[i]; }
    for (int i = tid; i < 20;   i += 128) sm[B2 + i] = b2[i];
    for (int i = tid; i < 400;  i += 128) { int j = i / 20, k = i % 20; sm[W3T + k*20 + j] = w3[i]; }
    for (int i = tid; i < 20;   i += 128) sm[B3 + i] = b3[i];
    for (int i = tid; i < 240;  i += 128) { int k = i / 12, j = i % 12; sm[W4T + i] = (j < 10) ? w4[j*20 + k] : 0.f; }
    for (int i = tid; i < 12;   i += 128) sm[B4 + i] = (i < 10) ? b4[i] : 0.f;
    for (int i = tid; i < 12;   i += 128) sm[WF + i] = (i < 10) ? wf[i] : 0.f;
    if (tid == 0) { sm[SC] = wscal[0]; sm[SC + 1] = bf[0]; }

    // ---- per-node message-pass coefficients + node weight ----
    float cs[7];
    float wt = 0.f;
    if (valid) {
        wt = wts[n];
        float c0a = nbc[n*6+0], c0b = nbc[n*6+1], c0c = nbc[n*6+2];
        float c1a = nbc[n*6+3], c1b = nbc[n*6+4], c1c = nbc[n*6+5];
        float w_ = wscal[0];
        float nb0 = c0a + c0b + c0c, nb1 = c1a + c1b + c1c;
        float nb0s = (nb0 < 1e-5f) ? 1e-5f : nb0;
        float nb1s = (nb1 < 1e-5f) ? 1e-5f : nb1;
        float h0 = (nb0 > 0.f) ? 1.f : 0.f;
        float h1 = (nb1 > 0.f) ? 1.f : 0.f;
        float inv0 = w_ / nb0s, inv1 = w_ / nb1s;
        cs[0] = 1.f - h0 * w_ - h1 * w_;
        cs[1] = c0a * inv0; cs[2] = c0b * inv0; cs[3] = c0c * inv0;
        cs[4] = c1a * inv1; cs[5] = c1b * inv1; cs[6] = c1c * inv1;
    }

    u64 m[10];
    #pragma unroll
    for (int j = 0; j < 10; j++) m[j] = 0ull;

    const float* xrow = &sm[XB + tid * 44];

    // p0: compute (s0,s1) from slots 0,1; then refill slots 0,1 with (s4,s5)
    asm volatile("cp.async.wait_group 1;");
    __syncthreads();
    if (valid) compute_pair(sm, xrow + 0*XBSZ, xrow + 1*XBSZ, cs[0], cs[1], m);
    __syncthreads();
    STAGE(0, 4); STAGE(1, 5);
    asm volatile("cp.async.commit_group;");

    // p1: compute (s2,s3) from slots 2,3; then refill slot 2 with s6
    asm volatile("cp.async.wait_group 1;");
    __syncthreads();
    if (valid) compute_pair(sm, xrow + 2*XBSZ, xrow + 3*XBSZ, cs[2], cs[3], m);
    __syncthreads();
    STAGE(2, 6);
    asm volatile("cp.async.commit_group;");

    // p2: compute (s4,s5) from slots 0,1
    asm volatile("cp.async.wait_group 1;");
    __syncthreads();
    if (valid) compute_pair(sm, xrow + 0*XBSZ, xrow + 1*XBSZ, cs[4], cs[5], m);

    // tail: compute s6 as degenerate pair (second column weighted 0)
    asm volatile("cp.async.wait_group 0;");
    __syncthreads();
    if (valid) compute_pair(sm, xrow + 2*XBSZ, xrow + 2*XBSZ, cs[6], 0.f, m);

    float contrib = 0.f;
    if (valid) {
        float mt[20];
        #pragma unroll
        for (int j = 0; j < 10; j++) upk(m[j], mt[2*j+0], mt[2*j+1]);

        // ---- fc1 layer 0: 20 -> 20 ----
        u64 p[10];
        const u64* bp3 = (const u64*)&sm[B3];
        #pragma unroll
        for (int j = 0; j < 10; j++) p[j] = bp3[j];
        #pragma unroll
        for (int k = 0; k < 20; k++) {
            u64 xx = pk2(mt[k]);
            const ulonglong2* wr = (const ulonglong2*)&sm[W3T + k * 20];
            #pragma unroll
            for (int j2 = 0; j2 < 5; j2++) {
                ulonglong2 wv = wr[j2];
                p[2*j2+0] = ffma2(xx, wv.x, p[2*j2+0]);
                p[2*j2+1] = ffma2(xx, wv.y, p[2*j2+1]);
            }
        }
        float pt[20];
        #pragma unroll
        for (int j = 0; j < 10; j++) {
            float a, c; upk(p[j], a, c);
            pt[2*j+0] = fast_tanh(a);
            pt[2*j+1] = fast_tanh(c);
        }

        // ---- fc1 layer 1: 20 -> 10 (padded to 12) ----
        u64 q[6];
        const u64* bp4 = (const u64*)&sm[B4];
        #pragma unroll
        for (int j = 0; j < 6; j++) q[j] = bp4[j];
        #pragma unroll
        for (int k = 0; k < 20; k++) {
            u64 xx = pk2(pt[k]);
            const ulonglong2* wr = (const ulonglong2*)&sm[W4T + k * 12];
            #pragma unroll
            for (int j2 = 0; j2 < 3; j2++) {
                ulonglong2 wv = wr[j2];
                q[2*j2+0] = ffma2(xx, wv.x, q[2*j2+0]);
                q[2*j2+1] = ffma2(xx, wv.y, q[2*j2+1]);
            }
        }

        // ---- head: 10 -> 1 ---- (padded lanes have wf=0)
        float e = sm[SC + 1];
        #pragma unroll
        for (int j = 0; j < 6; j++) {
            float a, c; upk(q[j], a, c);
            e += fast_tanh(a) * sm[WF + 2*j + 0];
            e += fast_tanh(c) * sm[WF + 2*j + 1];
        }
        contrib = wt * e;
    }

    // ---- block reduce + one atomic ----
    __syncthreads();
    sm[RED + tid] = contrib;
    __syncthreads();
    #pragma unroll
    for (int o = 64; o > 0; o >>= 1) {
        if (tid < o) sm[RED + tid] += sm[RED + tid + o];
        __syncthreads();
    }
    if (tid == 0) atomicAdd(&out[b], SIGMA_C * sm[RED]);
    #undef STAGE
}

extern "C" void kernel_launch(void* const* d_in, const int* in_sizes, int n_in,
                              void* d_out, int out_size)
{
    const float* feat  = (const float*)d_in[0];
    const float* nbc   = (const float*)d_in[1];
    const float* wts   = (const float*)d_in[2];
    const float* wscal = (const float*)d_in[3];
    const float* w0 = (const float*)d_in[4];
    const float* b0 = (const float*)d_in[5];
    const float* w1 = (const float*)d_in[6];
    const float* b1 = (const float*)d_in[7];
    const float* w2 = (const float*)d_in[8];
    const float* b2 = (const float*)d_in[9];
    const float* w3 = (const float*)d_in[10];
    const float* b3 = (const float*)d_in[11];
    const float* w4 = (const float*)d_in[12];
    const float* b4 = (const float*)d_in[13];
    const float* wf = (const float*)d_in[14];
    const float* bf = (const float*)d_in[15];
    float* out = (float*)d_out;

    const int N = in_sizes[2];
    const int B = out_size;

    cudaFuncSetAttribute(gnn_kernel, cudaFuncAttributeMaxDynamicSharedMemorySize, SMEM_BYTES);

    init_out_kernel<<<1, 32>>>(out, B);
    dim3 grid((N + 127) / 128, B);
    gnn_kernel<<<grid, 128, SMEM_BYTES>>>(feat, nbc, wts, wscal,
                                          w0, b0, w1, b1, w2, b2,
                                          w3, b3, w4, b4, wf, bf,
                                          out, N);
}

// round 5
// speedup vs baseline: 5.0896x; 1.2062x over previous
#include <cuda_runtime.h>
#include <cstdint>

#define SIGMA_C 162.13039087945623f
#define MU_C    117.41975505778706f

typedef unsigned long long u64;
typedef unsigned int u32;

__device__ __forceinline__ float fast_tanh(float x) {
    float y;
    asm("tanh.approx.f32 %0, %1;" : "=f"(y) : "f"(x));
    return y;
}
__device__ __forceinline__ u64 pk2(float x) {
    u64 r; asm("mov.b64 %0, {%1, %1};" : "=l"(r) : "f"(x)); return r;
}
__device__ __forceinline__ u64 pk(float a, float b) {
    u64 r; asm("mov.b64 %0, {%1, %2};" : "=l"(r) : "f"(a), "f"(b)); return r;
}
__device__ __forceinline__ void upk(u64 v, float& a, float& b) {
    asm("mov.b64 {%0, %1}, %2;" : "=f"(a), "=f"(b) : "l"(v));
}
__device__ __forceinline__ u64 ffma2(u64 a, u64 b, u64 c) {
    u64 d; asm("fma.rn.f32x2 %0, %1, %2, %3;" : "=l"(d) : "l"(a), "l"(b), "l"(c)); return d;
}

__global__ void __launch_bounds__(32) init_out_kernel(float* out, int B) {
    int i = threadIdx.x;
    if (i < B) out[i] = MU_C;
}

// float offsets in dynamic smem
#define W0T 0
#define B0  1600
#define W1T 1640
#define B1  2440
#define W2T 2460
#define B2  2860
#define W3T 2880
#define B3  3280
#define W4T 3300
#define B4  3540
#define WF  3552
#define SC  3564
#define XB  3584
#define XBSZ (128*44)
#define MS  (XB + 2*XBSZ)          /* m scratch: 128 rows x 20 floats */
#define RED (MS + 128*20)
#define SMEM_FLOATS (RED + 128)
#define SMEM_BYTES (SMEM_FLOATS * 4)   /* 70.1 KB -> 3 blocks/SM */

// Fused fc0-layer0 -> tanh -> fc0-layer1 for TWO s-columns sharing every
// weight LDS. Layer0 output is produced in 20-wide chunks so the h register
// footprint stays at 10 u64 per column.
__device__ __forceinline__ void pair01(
    const float* __restrict__ sm,
    const float* __restrict__ xr0, const float* __restrict__ xr1,
    u64* __restrict__ g0, u64* __restrict__ g1)
{
    const u64* bp1 = (const u64*)&sm[B1];
    #pragma unroll
    for (int j = 0; j < 10; j++) { g0[j] = bp1[j]; g1[j] = bp1[j]; }

    #pragma unroll 1
    for (int c = 0; c < 2; c++) {
        u64 h0[10], h1[10];
        const u64* bp0 = (const u64*)&sm[B0 + 20*c];
        #pragma unroll
        for (int j = 0; j < 10; j++) { h0[j] = bp0[j]; h1[j] = bp0[j]; }
        #pragma unroll
        for (int kk = 0; kk < 10; kk++) {
            float4 xa = *(const float4*)&xr0[kk * 4];
            float4 xb = *(const float4*)&xr1[kk * 4];
            float xa4[4] = {xa.x, xa.y, xa.z, xa.w};
            float xb4[4] = {xb.x, xb.y, xb.z, xb.w};
            #pragma unroll
            for (int u = 0; u < 4; u++) {
                u64 xxa = pk2(xa4[u]);
                u64 xxb = pk2(xb4[u]);
                const ulonglong2* wr = (const ulonglong2*)&sm[W0T + (kk*4 + u)*40 + 20*c];
                #pragma unroll
                for (int j2 = 0; j2 < 5; j2++) {
                    ulonglong2 wv = wr[j2];
                    h0[2*j2+0] = ffma2(xxa, wv.x, h0[2*j2+0]);
                    h0[2*j2+1] = ffma2(xxa, wv.y, h0[2*j2+1]);
                    h1[2*j2+0] = ffma2(xxb, wv.x, h1[2*j2+0]);
                    h1[2*j2+1] = ffma2(xxb, wv.y, h1[2*j2+1]);
                }
            }
        }
        // tanh + layer1 accumulate: k = 20c + 2jj (+1)
        #pragma unroll
        for (int jj = 0; jj < 10; jj++) {
            float a0, b0v, a1, b1v;
            upk(h0[jj], a0, b0v);
            upk(h1[jj], a1, b1v);
            {
                u64 xxa = pk2(fast_tanh(a0));
                u64 xxb = pk2(fast_tanh(a1));
                const ulonglong2* wr = (const ulonglong2*)&sm[W1T + (20*c + 2*jj)*20];
                #pragma unroll
                for (int j2 = 0; j2 < 5; j2++) {
                    ulonglong2 wv = wr[j2];
                    g0[2*j2+0] = ffma2(xxa, wv.x, g0[2*j2+0]);
                    g0[2*j2+1] = ffma2(xxa, wv.y, g0[2*j2+1]);
                    g1[2*j2+0] = ffma2(xxb, wv.x, g1[2*j2+0]);
                    g1[2*j2+1] = ffma2(xxb, wv.y, g1[2*j2+1]);
                }
            }
            {
                u64 xxa = pk2(fast_tanh(b0v));
                u64 xxb = pk2(fast_tanh(b1v));
                const ulonglong2* wr = (const ulonglong2*)&sm[W1T + (20*c + 2*jj + 1)*20];
                #pragma unroll
                for (int j2 = 0; j2 < 5; j2++) {
                    ulonglong2 wv = wr[j2];
                    g0[2*j2+0] = ffma2(xxa, wv.x, g0[2*j2+0]);
                    g0[2*j2+1] = ffma2(xxa, wv.y, g0[2*j2+1]);
                    g1[2*j2+0] = ffma2(xxb, wv.x, g1[2*j2+0]);
                    g1[2*j2+1] = ffma2(xxb, wv.y, g1[2*j2+1]);
                }
            }
        }
    }
}

// fc0-layer2 + message accumulate for the pair (reads weights + m only).
__device__ __forceinline__ void pair2(
    const float* __restrict__ sm,
    const u64* __restrict__ g0, const u64* __restrict__ g1,
    float ca, float cb, float* __restrict__ mrow)
{
    float gt0[20], gt1[20];
    #pragma unroll
    for (int j = 0; j < 10; j++) {
        float a, b;
        upk(g0[j], a, b); gt0[2*j+0] = fast_tanh(a); gt0[2*j+1] = fast_tanh(b);
        upk(g1[j], a, b); gt1[2*j+0] = fast_tanh(a); gt1[2*j+1] = fast_tanh(b);
    }
    u64 t0[10], t1[10];
    const u64* bp2 = (const u64*)&sm[B2];
    #pragma unroll
    for (int j = 0; j < 10; j++) { t0[j] = bp2[j]; t1[j] = bp2[j]; }
    #pragma unroll
    for (int k = 0; k < 20; k++) {
        u64 xxa = pk2(gt0[k]);
        u64 xxb = pk2(gt1[k]);
        const ulonglong2* wr = (const ulonglong2*)&sm[W2T + k * 20];
        #pragma unroll
        for (int j2 = 0; j2 < 5; j2++) {
            ulonglong2 wv = wr[j2];
            t0[2*j2+0] = ffma2(xxa, wv.x, t0[2*j2+0]);
            t0[2*j2+1] = ffma2(xxa, wv.y, t0[2*j2+1]);
            t1[2*j2+0] = ffma2(xxb, wv.x, t1[2*j2+0]);
            t1[2*j2+1] = ffma2(xxb, wv.y, t1[2*j2+1]);
        }
    }
    u64 cxa = pk2(ca), cxb = pk2(cb);
    u64* mp = (u64*)mrow;
    #pragma unroll
    for (int j = 0; j < 10; j++) {
        u64 acc = mp[j];
        float a, b;
        upk(t0[j], a, b); acc = ffma2(cxa, pk(fast_tanh(a), fast_tanh(b)), acc);
        upk(t1[j], a, b); acc = ffma2(cxb, pk(fast_tanh(a), fast_tanh(b)), acc);
        mp[j] = acc;
    }
}

// Single-column versions for the odd 7th s-column.
__device__ __forceinline__ void single01(
    const float* __restrict__ sm, const float* __restrict__ xr0,
    u64* __restrict__ g0)
{
    const u64* bp1 = (const u64*)&sm[B1];
    #pragma unroll
    for (int j = 0; j < 10; j++) g0[j] = bp1[j];
    #pragma unroll 1
    for (int c = 0; c < 2; c++) {
        u64 h0[10];
        const u64* bp0 = (const u64*)&sm[B0 + 20*c];
        #pragma unroll
        for (int j = 0; j < 10; j++) h0[j] = bp0[j];
        #pragma unroll
        for (int kk = 0; kk < 10; kk++) {
            float4 xa = *(const float4*)&xr0[kk * 4];
            float xa4[4] = {xa.x, xa.y, xa.z, xa.w};
            #pragma unroll
            for (int u = 0; u < 4; u++) {
                u64 xxa = pk2(xa4[u]);
                const ulonglong2* wr = (const ulonglong2*)&sm[W0T + (kk*4 + u)*40 + 20*c];
                #pragma unroll
                for (int j2 = 0; j2 < 5; j2++) {
                    ulonglong2 wv = wr[j2];
                    h0[2*j2+0] = ffma2(xxa, wv.x, h0[2*j2+0]);
                    h0[2*j2+1] = ffma2(xxa, wv.y, h0[2*j2+1]);
                }
            }
        }
        #pragma unroll
        for (int jj = 0; jj < 10; jj++) {
            float a0, b0v;
            upk(h0[jj], a0, b0v);
            {
                u64 xxa = pk2(fast_tanh(a0));
                const ulonglong2* wr = (const ulonglong2*)&sm[W1T + (20*c + 2*jj)*20];
                #pragma unroll
                for (int j2 = 0; j2 < 5; j2++) {
                    ulonglong2 wv = wr[j2];
                    g0[2*j2+0] = ffma2(xxa, wv.x, g0[2*j2+0]);
                    g0[2*j2+1] = ffma2(xxa, wv.y, g0[2*j2+1]);
                }
            }
            {
                u64 xxa = pk2(fast_tanh(b0v));
                const ulonglong2* wr = (const ulonglong2*)&sm[W1T + (20*c + 2*jj + 1)*20];
                #pragma unroll
                for (int j2 = 0; j2 < 5; j2++) {
                    ulonglong2 wv = wr[j2];
                    g0[2*j2+0] = ffma2(xxa, wv.x, g0[2*j2+0]);
                    g0[2*j2+1] = ffma2(xxa, wv.y, g0[2*j2+1]);
                }
            }
        }
    }
}

__device__ __forceinline__ void single2(
    const float* __restrict__ sm, const u64* __restrict__ g0,
    float ca, float* __restrict__ mrow)
{
    float gt0[20];
    #pragma unroll
    for (int j = 0; j < 10; j++) {
        float a, b;
        upk(g0[j], a, b); gt0[2*j+0] = fast_tanh(a); gt0[2*j+1] = fast_tanh(b);
    }
    u64 t0[10];
    const u64* bp2 = (const u64*)&sm[B2];
    #pragma unroll
    for (int j = 0; j < 10; j++) t0[j] = bp2[j];
    #pragma unroll
    for (int k = 0; k < 20; k++) {
        u64 xxa = pk2(gt0[k]);
        const ulonglong2* wr = (const ulonglong2*)&sm[W2T + k * 20];
        #pragma unroll
        for (int j2 = 0; j2 < 5; j2++) {
            ulonglong2 wv = wr[j2];
            t0[2*j2+0] = ffma2(xxa, wv.x, t0[2*j2+0]);
            t0[2*j2+1] = ffma2(xxa, wv.y, t0[2*j2+1]);
        }
    }
    u64 cxa = pk2(ca);
    u64* mp = (u64*)mrow;
    #pragma unroll
    for (int j = 0; j < 10; j++) {
        float a, b;
        upk(t0[j], a, b);
        mp[j] = ffma2(cxa, pk(fast_tanh(a), fast_tanh(b)), mp[j]);
    }
}

__global__ void __launch_bounds__(128, 3) gnn_kernel(
    const float* __restrict__ feat,
    const float* __restrict__ nbc,
    const float* __restrict__ wts,
    const float* __restrict__ wscal,
    const float* __restrict__ w0, const float* __restrict__ b0,
    const float* __restrict__ w1, const float* __restrict__ b1,
    const float* __restrict__ w2, const float* __restrict__ b2,
    const float* __restrict__ w3, const float* __restrict__ b3,
    const float* __restrict__ w4, const float* __restrict__ b4,
    const float* __restrict__ wf, const float* __restrict__ bf,
    float* __restrict__ out, int N)
{
    extern __shared__ float sm[];
    const int tid = threadIdx.x;
    const int n0  = blockIdx.x * 128;
    const int b   = blockIdx.y;
    const int n   = n0 + tid;
    const bool valid = (n < N);
    const int nvalid = (N - n0 < 128) ? (N - n0) : 128;

    const float4* fb = reinterpret_cast<const float4*>(feat) + ((size_t)b * N + n0) * 70;

    #define STAGE(slot, sidx)                                                          \
        {                                                                              \
            _Pragma("unroll")                                                          \
            for (int it = 0; it < 10; it++) {                                          \
                int i = it * 128 + tid;                                                \
                int row = i / 10, q = i % 10;                                          \
                if (row < nvalid) {                                                    \
                    u32 dst = (u32)__cvta_generic_to_shared(                           \
                        &sm[XB + (slot)*XBSZ + row * 44 + q * 4]);                     \
                    const float4* src = fb + row * 70 + (sidx) * 10 + q;               \
                    asm volatile("cp.async.ca.shared.global [%0], [%1], 16;"           \
                                 :: "r"(dst), "l"(src));                               \
                }                                                                      \
            }                                                                          \
        }

    // Preload pair (s0,s1).
    STAGE(0, 0); STAGE(1, 1);
    asm volatile("cp.async.commit_group;");

    // ---- cooperative weight load + transpose (overlaps with cp.async) ----
    for (int i = tid; i < 1600; i += 128) { int j = i / 40, k = i % 40; sm[W0T + k*40 + j] = w0[i]; }
    for (int i = tid; i < 40;   i += 128) sm[B0 + i] = b0[i];
    for (int i = tid; i < 800;  i += 128) { int j = i / 40, k = i % 40; sm[W1T + k*20 + j] = w1[i]; }
    for (int i = tid; i < 20;   i += 128) sm[B1 + i] = b1[i];
    for (int i = tid; i < 400;  i += 128) { int j = i / 20, k = i % 20; sm[W2T + k*20 + j] = w2[i]; }
    for (int i = tid; i < 20;   i += 128) sm[B2 + i] = b2[i];
    for (int i = tid; i < 400;  i += 128) { int j = i / 20, k = i % 20; sm[W3T + k*20 + j] = w3[i]; }
    for (int i = tid; i < 20;   i += 128) sm[B3 + i] = b3[i];
    for (int i = tid; i < 240;  i += 128) { int k = i / 12, j = i % 12; sm[W4T + i] = (j < 10) ? w4[j*20 + k] : 0.f; }
    for (int i = tid; i < 12;   i += 128) sm[B4 + i] = (i < 10) ? b4[i] : 0.f;
    for (int i = tid; i < 12;   i += 128) sm[WF + i] = (i < 10) ? wf[i] : 0.f;
    if (tid == 0) { sm[SC] = wscal[0]; sm[SC + 1] = bf[0]; }

    // ---- per-node message-pass coefficients + node weight ----
    float cs[7];
    float wt = 0.f;
    if (valid) {
        wt = wts[n];
        float c0a = nbc[n*6+0], c0b = nbc[n*6+1], c0c = nbc[n*6+2];
        float c1a = nbc[n*6+3], c1b = nbc[n*6+4], c1c = nbc[n*6+5];
        float w_ = wscal[0];
        float nb0 = c0a + c0b + c0c, nb1 = c1a + c1b + c1c;
        float nb0s = (nb0 < 1e-5f) ? 1e-5f : nb0;
        float nb1s = (nb1 < 1e-5f) ? 1e-5f : nb1;
        float h0 = (nb0 > 0.f) ? 1.f : 0.f;
        float h1 = (nb1 > 0.f) ? 1.f : 0.f;
        float inv0 = w_ / nb0s, inv1 = w_ / nb1s;
        cs[0] = 1.f - h0 * w_ - h1 * w_;
        cs[1] = c0a * inv0; cs[2] = c0b * inv0; cs[3] = c0c * inv0;
        cs[4] = c1a * inv1; cs[5] = c1b * inv1; cs[6] = c1c * inv1;
    }

    float* mrow = &sm[MS + tid * 20];
    {
        u64* mp = (u64*)mrow;
        #pragma unroll
        for (int j = 0; j < 10; j++) mp[j] = 0ull;
    }

    const float* xr0 = &sm[XB + tid * 44];
    const float* xr1 = &sm[XB + XBSZ + tid * 44];
    u64 g0[10], g1[10];

    // pair 0: (s0,s1)
    asm volatile("cp.async.wait_group 0;");
    __syncthreads();
    if (valid) pair01(sm, xr0, xr1, g0, g1);
    __syncthreads();
    STAGE(0, 2); STAGE(1, 3);
    asm volatile("cp.async.commit_group;");
    if (valid) pair2(sm, g0, g1, cs[0], cs[1], mrow);

    // pair 1: (s2,s3)
    asm volatile("cp.async.wait_group 0;");
    __syncthreads();
    if (valid) pair01(sm, xr0, xr1, g0, g1);
    __syncthreads();
    STAGE(0, 4); STAGE(1, 5);
    asm volatile("cp.async.commit_group;");
    if (valid) pair2(sm, g0, g1, cs[2], cs[3], mrow);

    // pair 2: (s4,s5)
    asm volatile("cp.async.wait_group 0;");
    __syncthreads();
    if (valid) pair01(sm, xr0, xr1, g0, g1);
    __syncthreads();
    STAGE(0, 6);
    asm volatile("cp.async.commit_group;");
    if (valid) pair2(sm, g0, g1, cs[4], cs[5], mrow);

    // single: s6
    asm volatile("cp.async.wait_group 0;");
    __syncthreads();
    if (valid) {
        single01(sm, xr0, g0);
        single2(sm, g0, cs[6], mrow);
    }

    float contrib = 0.f;
    if (valid) {
        float mt[20];
        {
            const u64* mp = (const u64*)mrow;
            #pragma unroll
            for (int j = 0; j < 10; j++) upk(mp[j], mt[2*j+0], mt[2*j+1]);
        }

        // ---- fc1 layer 0: 20 -> 20 ----
        u64 p[10];
        const u64* bp3 = (const u64*)&sm[B3];
        #pragma unroll
        for (int j = 0; j < 10; j++) p[j] = bp3[j];
        #pragma unroll
        for (int k = 0; k < 20; k++) {
            u64 xx = pk2(mt[k]);
            const ulonglong2* wr = (const ulonglong2*)&sm[W3T + k * 20];
            #pragma unroll
            for (int j2 = 0; j2 < 5; j2++) {
                ulonglong2 wv = wr[j2];
                p[2*j2+0] = ffma2(xx, wv.x, p[2*j2+0]);
                p[2*j2+1] = ffma2(xx, wv.y, p[2*j2+1]);
            }
        }
        float pt[20];
        #pragma unroll
        for (int j = 0; j < 10; j++) {
            float a, c; upk(p[j], a, c);
            pt[2*j+0] = fast_tanh(a);
            pt[2*j+1] = fast_tanh(c);
        }

        // ---- fc1 layer 1: 20 -> 10 (padded to 12) ----
        u64 q[6];
        const u64* bp4 = (const u64*)&sm[B4];
        #pragma unroll
        for (int j = 0; j < 6; j++) q[j] = bp4[j];
        #pragma unroll
        for (int k = 0; k < 20; k++) {
            u64 xx = pk2(pt[k]);
            const ulonglong2* wr = (const ulonglong2*)&sm[W4T + k * 12];
            #pragma unroll
            for (int j2 = 0; j2 < 3; j2++) {
                ulonglong2 wv = wr[j2];
                q[2*j2+0] = ffma2(xx, wv.x, q[2*j2+0]);
                q[2*j2+1] = ffma2(xx, wv.y, q[2*j2+1]);
            }
        }

        // ---- head: 10 -> 1 ---- (padded lanes have wf=0)
        float e = sm[SC + 1];
        #pragma unroll
        for (int j = 0; j < 6; j++) {
            float a, c; upk(q[j], a, c);
            e += fast_tanh(a) * sm[WF + 2*j + 0];
            e += fast_tanh(c) * sm[WF + 2*j + 1];
        }
        contrib = wt * e;
    }

    // ---- block reduce + one atomic ----
    __syncthreads();
    sm[RED + tid] = contrib;
    __syncthreads();
    #pragma unroll
    for (int o = 64; o > 0; o >>= 1) {
        if (tid < o) sm[RED + tid] += sm[RED + tid + o];
        __syncthreads();
    }
    if (tid == 0) atomicAdd(&out[b], SIGMA_C * sm[RED]);
    #undef STAGE
}

extern "C" void kernel_launch(void* const* d_in, const int* in_sizes, int n_in,
                              void* d_out, int out_size)
{
    const float* feat  = (const float*)d_in[0];
    const float* nbc   = (const float*)d_in[1];
    const float* wts   = (const float*)d_in[2];
    const float* wscal = (const float*)d_in[3];
    const float* w0 = (const float*)d_in[4];
    const float* b0 = (const float*)d_in[5];
    const float* w1 = (const float*)d_in[6];
    const float* b1 = (const float*)d_in[7];
    const float* w2 = (const float*)d_in[8];
    const float* b2 = (const float*)d_in[9];
    const float* w3 = (const float*)d_in[10];
    const float* b3 = (const float*)d_in[11];
    const float* w4 = (const float*)d_in[12];
    const float* b4 = (const float*)d_in[13];
    const float* wf = (const float*)d_in[14];
    const float* bf = (const float*)d_in[15];
    float* out = (float*)d_out;

    const int N = in_sizes[2];
    const int B = out_size;

    cudaFuncSetAttribute(gnn_kernel, cudaFuncAttributeMaxDynamicSharedMemorySize, SMEM_BYTES);

    init_out_kernel<<<1, 32>>>(out, B);
    dim3 grid((N + 127) / 128, B);
    gnn_kernel<<<grid, 128, SMEM_BYTES>>>(feat, nbc, wts, wscal,
                                          w0, b0, w1, b1, w2, b2,
                                          w3, b3, w4, b4, wf, bf,
                                          out, N);
}

// round 7
// speedup vs baseline: 9.3617x; 1.8394x over previous
#include <cuda_runtime.h>
#include <cuda_bf16.h>
#include <cstdint>

typedef unsigned int u32;
typedef unsigned long long u64;

#define SIGMA_C 162.13039087945623f
#define MU_C    117.41975505778706f

// ---- smem byte offsets ----
#define P_OFF     0        /* 448 rows x 20 floats = 35840 B (overlaid by W*p during init) */
#define W0P_OFF   0        /* 40 x 48 f32 */
#define W1P_OFF   7680     /* 24 x 48 f32 */
#define W2P_OFF   12288    /* 24 x 32 f32 */
#define X_OFF     35840    /* 64 rows x 112 B bf16 (56 cols, 40 real) */
#define ST0_OFF   43008    /* 64 rows x 176 B fp32 staging */
#define ST1_OFF   54272
#define CS_OFF    65536    /* 448 f32 coefficients */
#define BIAS0_OFF 67328    /* 48 f32 */
#define BIAS1_OFF 67520    /* 24 f32 */
#define BIAS2_OFF 67616    /* 24 f32 */
#define FCW_OFF   67712    /* 686 f32 fc1/head */
#define RED_OFF   70464    /* 128 f32 */
#define SMEM_BYTES 71168

static __device__ __forceinline__ u32 smem_u32(const void* p) {
    u32 a;
    asm("{ .reg .u64 t; cvta.to.shared.u64 t, %1; cvt.u32.u64 %0, t; }" : "=r"(a) : "l"(p));
    return a;
}
static __device__ __forceinline__ float fast_tanh(float x) {
    float y; asm("tanh.approx.f32 %0, %1;" : "=f"(y) : "f"(x)); return y;
}
// pack two f32 -> bf16x2 (lo = first arg)
#define CVT2(res, lo, hi) \
    asm("cvt.rn.bf16x2.f32 %0, %1, %2;" : "=r"(res) : "f"(hi), "f"(lo))

static __device__ __forceinline__ void mma16816(float* d, const u32* a, const u32* b) {
    asm volatile("mma.sync.aligned.m16n8k16.row.col.f32.bf16.bf16.f32 "
        "{%0,%1,%2,%3}, {%4,%5,%6,%7}, {%8,%9}, {%0,%1,%2,%3};"
        : "+f"(d[0]), "+f"(d[1]), "+f"(d[2]), "+f"(d[3])
        : "r"(a[0]), "r"(a[1]), "r"(a[2]), "r"(a[3]), "r"(b[0]), "r"(b[1]));
}
static __device__ __forceinline__ void ldm4(u32* r, u32 addr) {
    asm volatile("ldmatrix.sync.aligned.m8n8.x4.shared.b16 {%0,%1,%2,%3}, [%4];"
        : "=r"(r[0]), "=r"(r[1]), "=r"(r[2]), "=r"(r[3]) : "r"(addr));
}

// f32x2 helpers (fc1 tail)
static __device__ __forceinline__ u64 pk2(float x) {
    u64 r; asm("mov.b64 %0, {%1, %1};" : "=l"(r) : "f"(x)); return r;
}
static __device__ __forceinline__ void upk(u64 v, float& a, float& b) {
    asm("mov.b64 {%0, %1}, %2;" : "=f"(a), "=f"(b) : "l"(v));
}
static __device__ __forceinline__ u64 ffma2(u64 a, u64 b, u64 c) {
    u64 d; asm("fma.rn.f32x2 %0, %1, %2, %3;" : "=l"(d) : "l"(a), "l"(b), "l"(c)); return d;
}

__global__ void __launch_bounds__(32) init_out_kernel(float* out, int B) {
    int i = threadIdx.x;
    if (i < B) out[i] = MU_C;
}

__global__ void __launch_bounds__(128, 3) gnn_mma_kernel(
    const float* __restrict__ feat,
    const float* __restrict__ nbc,
    const float* __restrict__ wts,
    const float* __restrict__ wscal,
    const float* __restrict__ w0, const float* __restrict__ b0,
    const float* __restrict__ w1, const float* __restrict__ b1,
    const float* __restrict__ w2, const float* __restrict__ b2,
    const float* __restrict__ w3, const float* __restrict__ b3,
    const float* __restrict__ w4, const float* __restrict__ b4,
    const float* __restrict__ wf, const float* __restrict__ bff,
    float* __restrict__ out, int N)
{
    extern __shared__ char smem[];
    float* smf = (float*)smem;
    const int tid  = threadIdx.x;
    const int warp = tid >> 5;
    const int lane = tid & 31;
    const int bq = blockIdx.y;
    const int n0 = blockIdx.x * 64;
    const int nvalid = (N - n0 < 64) ? (N - n0) : 64;
    const int vrows = nvalid * 7;
    const u32 sb = smem_u32(smem);

    // ---- init: padded fp32 weights (overlay in P region), biases, fc1 weights, cs ----
    {
        float* w0p = smf + W0P_OFF / 4;
        for (int i = tid; i < 40 * 48; i += 128) { int n = i / 48, k = i % 48; w0p[i] = (k < 40) ? w0[n * 40 + k] : 0.f; }
        float* w1p = smf + W1P_OFF / 4;
        for (int i = tid; i < 24 * 48; i += 128) { int n = i / 48, k = i % 48; w1p[i] = (n < 20 && k < 40) ? w1[n * 40 + k] : 0.f; }
        float* w2p = smf + W2P_OFF / 4;
        for (int i = tid; i < 24 * 32; i += 128) { int n = i / 32, k = i % 32; w2p[i] = (n < 20 && k < 20) ? w2[n * 20 + k] : 0.f; }
        float* bb0 = smf + BIAS0_OFF / 4;
        for (int i = tid; i < 48; i += 128) bb0[i] = (i < 40) ? b0[i] : 0.f;
        float* bb1 = smf + BIAS1_OFF / 4;
        for (int i = tid; i < 24; i += 128) bb1[i] = (i < 20) ? b1[i] : 0.f;
        float* bb2 = smf + BIAS2_OFF / 4;
        for (int i = tid; i < 24; i += 128) bb2[i] = (i < 20) ? b2[i] : 0.f;
        float* fw = smf + FCW_OFF / 4;
        for (int i = tid; i < 400; i += 128) { int j = i / 20, k = i % 20; fw[k * 20 + j] = w3[i]; }
        for (int i = tid; i < 20;  i += 128) fw[400 + i] = b3[i];
        for (int i = tid; i < 240; i += 128) { int k = i / 12, j = i % 12; fw[420 + i] = (j < 10) ? w4[j * 20 + k] : 0.f; }
        for (int i = tid; i < 12;  i += 128) fw[660 + i] = (i < 10) ? b4[i] : 0.f;
        for (int i = tid; i < 12;  i += 128) fw[672 + i] = (i < 10) ? wf[i] : 0.f;
        if (tid == 0) { fw[684] = wscal[0]; fw[685] = bff[0]; }

        if (tid < 64) {
            float cs[7] = {0.f, 0.f, 0.f, 0.f, 0.f, 0.f, 0.f};
            int node = n0 + tid;
            if (node < N) {
                float c0a = nbc[node * 6 + 0], c0b = nbc[node * 6 + 1], c0c = nbc[node * 6 + 2];
                float c1a = nbc[node * 6 + 3], c1b = nbc[node * 6 + 4], c1c = nbc[node * 6 + 5];
                float w_ = wscal[0];
                float nb0 = c0a + c0b + c0c, nb1 = c1a + c1b + c1c;
                float nb0s = (nb0 < 1e-5f) ? 1e-5f : nb0;
                float nb1s = (nb1 < 1e-5f) ? 1e-5f : nb1;
                float h0 = (nb0 > 0.f) ? 1.f : 0.f;
                float h1 = (nb1 > 0.f) ? 1.f : 0.f;
                float inv0 = w_ / nb0s, inv1 = w_ / nb1s;
                cs[0] = 1.f - h0 * w_ - h1 * w_;
                cs[1] = c0a * inv0; cs[2] = c0b * inv0; cs[3] = c0c * inv0;
                cs[4] = c1a * inv1; cs[5] = c1b * inv1; cs[6] = c1c * inv1;
            }
            #pragma unroll
            for (int s = 0; s < 7; s++) smf[CS_OFF / 4 + tid * 7 + s] = cs[s];
        }
    }

    const float4* fb4 = (const float4*)feat + ((size_t)bq * N + n0) * 70;

    #define STAGE(bufoff, t)                                                        \
        {                                                                           \
            _Pragma("unroll")                                                       \
            for (int it = 0; it < 5; it++) {                                        \
                int i = it * 128 + tid;                                             \
                int row = i / 10, qq = i % 10;                                      \
                if ((t) * 64 + row < vrows) {                                       \
                    u32 dst = sb + (bufoff) + (u32)(row * 176 + qq * 16);           \
                    const float4* src = fb4 + ((size_t)((t) * 64 + row)) * 10 + qq; \
                    asm volatile("cp.async.ca.shared.global [%0], [%1], 16;"        \
                                 :: "r"(dst), "l"(src));                            \
                }                                                                   \
            }                                                                       \
            asm volatile("cp.async.commit_group;");                                 \
        }

    STAGE(ST0_OFF, 0);
    __syncthreads();   // weight tables ready for fragment load

    // ---- load B fragments into registers (persistent) ----
    const int q = lane & 3;
    const int nn = lane >> 2;
    u32 w0f[15][2], w1f[9][2], w2f[6][2];
    {
        const float* w0p = smf + W0P_OFF / 4;
        #pragma unroll
        for (int f = 0; f < 3; f++)
            #pragma unroll
            for (int j = 0; j < 5; j++) {
                int k0 = f * 16 + 2 * q;
                const float* r = &w0p[(j * 8 + nn) * 48];
                CVT2(w0f[f * 5 + j][0], r[k0 + 0], r[k0 + 1]);
                CVT2(w0f[f * 5 + j][1], r[k0 + 8], r[k0 + 9]);
            }
        const float* w1p = smf + W1P_OFF / 4;
        #pragma unroll
        for (int f = 0; f < 3; f++)
            #pragma unroll
            for (int j = 0; j < 3; j++) {
                int k0 = f * 16 + 2 * q;
                const float* r = &w1p[(j * 8 + nn) * 48];
                CVT2(w1f[f * 3 + j][0], r[k0 + 0], r[k0 + 1]);
                CVT2(w1f[f * 3 + j][1], r[k0 + 8], r[k0 + 9]);
            }
        const float* w2p = smf + W2P_OFF / 4;
        #pragma unroll
        for (int f = 0; f < 2; f++)
            #pragma unroll
            for (int j = 0; j < 3; j++) {
                int k0 = f * 16 + 2 * q;
                const float* r = &w2p[(j * 8 + nn) * 32];
                CVT2(w2f[f * 3 + j][0], r[k0 + 0], r[k0 + 1]);
                CVT2(w2f[f * 3 + j][1], r[k0 + 8], r[k0 + 9]);
            }
    }

    const float* bb0 = smf + BIAS0_OFF / 4;
    const float* bb1 = smf + BIAS1_OFF / 4;
    const float* bb2 = smf + BIAS2_OFF / 4;
    const float* csa = smf + CS_OFF / 4;

    // ldmatrix lane addressing
    const int lg = lane >> 3, lr = lane & 7;
    const int arow = warp * 16 + (lg & 1) * 8 + lr;
    const int acolb = (lg >> 1) * 8;

    #pragma unroll 1
    for (int t = 0; t < 7; t++) {
        if (t < 6) {
            if ((t + 1) & 1) { STAGE(ST1_OFF, t + 1); }
            else             { STAGE(ST0_OFF, t + 1); }
            asm volatile("cp.async.wait_group 1;");
        } else {
            asm volatile("cp.async.wait_group 0;");
        }
        __syncthreads();

        // ---- convert staged fp32 -> bf16 X tile (row pad to 56 cols / 112 B) ----
        {
            int row = tid >> 1, half = tid & 1;
            const float4* src = (const float4*)(smem + ((t & 1) ? ST1_OFF : ST0_OFF) + row * 176 + half * 80);
            u32* dst = (u32*)(smem + X_OFF + row * 112 + half * 40);
            #pragma unroll
            for (int c = 0; c < 5; c++) {
                float4 v = src[c];
                u32 p0, p1;
                CVT2(p0, v.x, v.y);
                CVT2(p1, v.z, v.w);
                dst[2 * c + 0] = p0;
                dst[2 * c + 1] = p1;
            }
            u32* pz = (u32*)(smem + X_OFF + row * 112 + 80 + half * 16);
            pz[0] = 0; pz[1] = 0; pz[2] = 0; pz[3] = 0;
        }
        __syncthreads();

        // ---- per-warp slab: 16 rows, full fc0 chain in registers ----
        {
            u32 a0f[3][4];
            #pragma unroll
            for (int f = 0; f < 3; f++)
                ldm4(a0f[f], sb + X_OFF + (u32)(arow * 112 + (f * 16 + acolb) * 2));

            // L0: 40 -> 40 (5 n-tiles)
            float d[5][4];
            #pragma unroll
            for (int j = 0; j < 5; j++) { d[j][0] = 0.f; d[j][1] = 0.f; d[j][2] = 0.f; d[j][3] = 0.f; }
            #pragma unroll
            for (int f = 0; f < 3; f++)
                #pragma unroll
                for (int j = 0; j < 5; j++)
                    mma16816(d[j], a0f[f], w0f[f * 5 + j]);

            // epilogue1: bias + tanh -> A1 fragments
            u32 a1f[3][4];
            #pragma unroll
            for (int j = 0; j < 5; j++) {
                int c0 = j * 8 + 2 * q;
                float bl = bb0[c0], bh = bb0[c0 + 1];
                float t0 = fast_tanh(d[j][0] + bl);
                float t1 = fast_tanh(d[j][1] + bh);
                float t2 = fast_tanh(d[j][2] + bl);
                float t3 = fast_tanh(d[j][3] + bh);
                u32 plo, phi;
                CVT2(plo, t0, t1);
                CVT2(phi, t2, t3);
                a1f[j >> 1][(j & 1) ? 2 : 0] = plo;
                a1f[j >> 1][(j & 1) ? 3 : 1] = phi;
            }
            a1f[2][2] = 0u; a1f[2][3] = 0u;

            // L1: 40 -> 20 (3 n-tiles)
            float e[3][4];
            #pragma unroll
            for (int j = 0; j < 3; j++) { e[j][0] = 0.f; e[j][1] = 0.f; e[j][2] = 0.f; e[j][3] = 0.f; }
            #pragma unroll
            for (int f = 0; f < 3; f++)
                #pragma unroll
                for (int j = 0; j < 3; j++)
                    mma16816(e[j], a1f[f], w1f[f * 3 + j]);

            // epilogue2: bias + tanh (cols >= 20 -> 0) -> A2 fragments
            u32 a2f[2][4];
            #pragma unroll
            for (int j = 0; j < 3; j++) {
                int c0 = j * 8 + 2 * q;
                float bl = bb1[c0], bh = bb1[c0 + 1];
                float t0 = (c0 < 20)     ? fast_tanh(e[j][0] + bl) : 0.f;
                float t1 = (c0 + 1 < 20) ? fast_tanh(e[j][1] + bh) : 0.f;
                float t2 = (c0 < 20)     ? fast_tanh(e[j][2] + bl) : 0.f;
                float t3 = (c0 + 1 < 20) ? fast_tanh(e[j][3] + bh) : 0.f;
                u32 plo, phi;
                CVT2(plo, t0, t1);
                CVT2(phi, t2, t3);
                a2f[j >> 1][(j & 1) ? 2 : 0] = plo;
                a2f[j >> 1][(j & 1) ? 3 : 1] = phi;
            }
            a2f[1][2] = 0u; a2f[1][3] = 0u;

            // L2: 20 -> 20 (3 n-tiles)
            float o[3][4];
            #pragma unroll
            for (int j = 0; j < 3; j++) { o[j][0] = 0.f; o[j][1] = 0.f; o[j][2] = 0.f; o[j][3] = 0.f; }
            #pragma unroll
            for (int f = 0; f < 2; f++)
                #pragma unroll
                for (int j = 0; j < 3; j++)
                    mma16816(o[j], a2f[f], w2f[f * 3 + j]);

            // epilogue3: cs * tanh(bias + v) -> P
            int r0 = t * 64 + warp * 16 + (lane >> 2);
            int r1 = r0 + 8;
            float cs0 = csa[r0], cs1 = csa[r1];
            #pragma unroll
            for (int j = 0; j < 3; j++) {
                int c0 = j * 8 + 2 * q;
                if (c0 < 20) {
                    float bl = bb2[c0], bh = bb2[c0 + 1];
                    float v0 = cs0 * fast_tanh(o[j][0] + bl);
                    float v1 = cs0 * fast_tanh(o[j][1] + bh);
                    float v2 = cs1 * fast_tanh(o[j][2] + bl);
                    float v3 = cs1 * fast_tanh(o[j][3] + bh);
                    *(float2*)(smem + P_OFF + (u32)(r0 * 80 + c0 * 4)) = make_float2(v0, v1);
                    *(float2*)(smem + P_OFF + (u32)(r1 * 80 + c0 * 4)) = make_float2(v2, v3);
                }
            }
        }
    }
    #undef STAGE
    __syncthreads();

    // ---- tail: gather P, fc1, head (threads 0..63) ----
    float contrib = 0.f;
    if (tid < nvalid) {
        const float* fw = smf + FCW_OFF / 4;
        float m[20];
        #pragma unroll
        for (int d = 0; d < 20; d++) m[d] = 0.f;
        #pragma unroll
        for (int s = 0; s < 7; s++) {
            const float4* pr = (const float4*)(smem + P_OFF + (u32)((tid * 7 + s) * 80));
            #pragma unroll
            for (int c = 0; c < 5; c++) {
                float4 vv = pr[c];
                m[4 * c + 0] += vv.x; m[4 * c + 1] += vv.y;
                m[4 * c + 2] += vv.z; m[4 * c + 3] += vv.w;
            }
        }

        // fc1 layer 0: 20 -> 20
        u64 p[10];
        const u64* bp3 = (const u64*)&fw[400];
        #pragma unroll
        for (int j = 0; j < 10; j++) p[j] = bp3[j];
        #pragma unroll
        for (int k = 0; k < 20; k++) {
            u64 xx = pk2(m[k]);
            const ulonglong2* wr = (const ulonglong2*)&fw[k * 20];
            #pragma unroll
            for (int j2 = 0; j2 < 5; j2++) {
                ulonglong2 wv = wr[j2];
                p[2 * j2 + 0] = ffma2(xx, wv.x, p[2 * j2 + 0]);
                p[2 * j2 + 1] = ffma2(xx, wv.y, p[2 * j2 + 1]);
            }
        }
        float pt[20];
        #pragma unroll
        for (int j = 0; j < 10; j++) {
            float a, c; upk(p[j], a, c);
            pt[2 * j + 0] = fast_tanh(a);
            pt[2 * j + 1] = fast_tanh(c);
        }

        // fc1 layer 1: 20 -> 10 (padded 12)
        u64 qq[6];
        const u64* bp4 = (const u64*)&fw[660];
        #pragma unroll
        for (int j = 0; j < 6; j++) qq[j] = bp4[j];
        #pragma unroll
        for (int k = 0; k < 20; k++) {
            u64 xx = pk2(pt[k]);
            const ulonglong2* wr = (const ulonglong2*)&fw[420 + k * 12];
            #pragma unroll
            for (int j2 = 0; j2 < 3; j2++) {
                ulonglong2 wv = wr[j2];
                qq[2 * j2 + 0] = ffma2(xx, wv.x, qq[2 * j2 + 0]);
                qq[2 * j2 + 1] = ffma2(xx, wv.y, qq[2 * j2 + 1]);
            }
        }

        float ev = fw[685];
        #pragma unroll
        for (int j = 0; j < 6; j++) {
            float a, c; upk(qq[j], a, c);
            ev += fast_tanh(a) * fw[672 + 2 * j + 0];
            ev += fast_tanh(c) * fw[672 + 2 * j + 1];
        }
        contrib = wts[n0 + tid] * ev;
    }

    // block reduce + one atomic
    float* red = smf + RED_OFF / 4;
    red[tid] = contrib;
    __syncthreads();
    #pragma unroll
    for (int o = 64; o > 0; o >>= 1) {
        if (tid < o) red[tid] += red[tid + o];
        __syncthreads();
    }
    if (tid == 0) atomicAdd(&out[bq], SIGMA_C * red[0]);
}

extern "C" void kernel_launch(void* const* d_in, const int* in_sizes, int n_in,
                              void* d_out, int out_size)
{
    const float* feat  = (const float*)d_in[0];
    const float* nbc   = (const float*)d_in[1];
    const float* wts   = (const float*)d_in[2];
    const float* wscal = (const float*)d_in[3];
    const float* w0 = (const float*)d_in[4];
    const float* b0 = (const float*)d_in[5];
    const float* w1 = (const float*)d_in[6];
    const float* b1 = (const float*)d_in[7];
    const float* w2 = (const float*)d_in[8];
    const float* b2 = (const float*)d_in[9];
    const float* w3 = (const float*)d_in[10];
    const float* b3 = (const float*)d_in[11];
    const float* w4 = (const float*)d_in[12];
    const float* b4 = (const float*)d_in[13];
    const float* wf = (const float*)d_in[14];
    const float* bff = (const float*)d_in[15];
    float* out = (float*)d_out;

    const int N = in_sizes[2];
    const int B = out_size;

    cudaFuncSetAttribute(gnn_mma_kernel, cudaFuncAttributeMaxDynamicSharedMemorySize, SMEM_BYTES);

    init_out_kernel<<<1, 32>>>(out, B);
    dim3 grid((N + 63) / 64, B);
    gnn_mma_kernel<<<grid, 128, SMEM_BYTES>>>(feat, nbc, wts, wscal,
                                              w0, b0, w1, b1, w2, b2,
                                              w3, b3, w4, b4, wf, bff,
                                              out, N);
}

// round 8
// speedup vs baseline: 16.8618x; 1.8011x over previous
#include <cuda_runtime.h>
#include <cuda_bf16.h>
#include <cstdint>

typedef unsigned int u32;
typedef unsigned long long u64;

#define SIGMA_C 162.13039087945623f
#define MU_C    117.41975505778706f

// ---- smem byte offsets ----
#define P_OFF     0        /* 448 rows x 20 floats = 35840 B (overlaid by W*p during init) */
#define W0P_OFF   0        /* 40 x 48 f32 */
#define W1P_OFF   7680     /* 24 x 48 f32 */
#define W2P_OFF   12288    /* 24 x 32 f32 */
#define X0_OFF    35840    /* 64 rows x 112 B bf16 */
#define X1_OFF    43008
#define CS_OFF    50176    /* 448 f32 coefficients */
#define BIAS0_OFF 51968
#define BIAS1_OFF 52160
#define BIAS2_OFF 52256
#define FCW_OFF   52352    /* 686 f32 fc1/head */
#define RED_OFF   55104    /* 128 f32 */
#define SMEM_BYTES 55616

static __device__ __forceinline__ u32 smem_u32(const void* p) {
    u32 a;
    asm("{ .reg .u64 t; cvta.to.shared.u64 t, %1; cvt.u32.u64 %0, t; }" : "=r"(a) : "l"(p));
    return a;
}
static __device__ __forceinline__ float fast_tanh(float x) {
    float y; asm("tanh.approx.f32 %0, %1;" : "=f"(y) : "f"(x)); return y;
}
#define CVT2(res, lo, hi) \
    asm("cvt.rn.bf16x2.f32 %0, %1, %2;" : "=r"(res) : "f"(hi), "f"(lo))

static __device__ __forceinline__ void mma16816(float* d, const u32* a, const u32* b) {
    asm volatile("mma.sync.aligned.m16n8k16.row.col.f32.bf16.bf16.f32 "
        "{%0,%1,%2,%3}, {%4,%5,%6,%7}, {%8,%9}, {%0,%1,%2,%3};"
        : "+f"(d[0]), "+f"(d[1]), "+f"(d[2]), "+f"(d[3])
        : "r"(a[0]), "r"(a[1]), "r"(a[2]), "r"(a[3]), "r"(b[0]), "r"(b[1]));
}
static __device__ __forceinline__ void ldm4(u32* r, u32 addr) {
    asm volatile("ldmatrix.sync.aligned.m8n8.x4.shared.b16 {%0,%1,%2,%3}, [%4];"
        : "=r"(r[0]), "=r"(r[1]), "=r"(r[2]), "=r"(r[3]) : "r"(addr));
}

static __device__ __forceinline__ u64 pk2(float x) {
    u64 r; asm("mov.b64 %0, {%1, %1};" : "=l"(r) : "f"(x)); return r;
}
static __device__ __forceinline__ void upk(u64 v, float& a, float& b) {
    asm("mov.b64 {%0, %1}, %2;" : "=f"(a), "=f"(b) : "l"(v));
}
static __device__ __forceinline__ u64 ffma2(u64 a, u64 b, u64 c) {
    u64 d; asm("fma.rn.f32x2 %0, %1, %2, %3;" : "=l"(d) : "l"(a), "l"(b), "l"(c)); return d;
}

__global__ void __launch_bounds__(32) init_out_kernel(float* out, int B) {
    int i = threadIdx.x;
    if (i < B) out[i] = MU_C;
}

__global__ void __launch_bounds__(128, 3) gnn_mma_kernel(
    const float* __restrict__ feat,
    const float* __restrict__ nbc,
    const float* __restrict__ wts,
    const float* __restrict__ wscal,
    const float* __restrict__ w0, const float* __restrict__ b0,
    const float* __restrict__ w1, const float* __restrict__ b1,
    const float* __restrict__ w2, const float* __restrict__ b2,
    const float* __restrict__ w3, const float* __restrict__ b3,
    const float* __restrict__ w4, const float* __restrict__ b4,
    const float* __restrict__ wf, const float* __restrict__ bff,
    float* __restrict__ out, int N, int B)
{
    extern __shared__ char smem[];
    float* smf = (float*)smem;
    const int tid  = threadIdx.x;
    const int warp = tid >> 5;
    const int lane = tid & 31;
    const int n0 = blockIdx.x * 64;
    const int nvalid = (N - n0 < 64) ? (N - n0) : 64;
    const int vrows = nvalid * 7;
    const u32 sb = smem_u32(smem);

    // ---- one-time init: padded weight tables (overlay P), biases, fc1, cs ----
    {
        float* w0p = smf + W0P_OFF / 4;
        for (int i = tid; i < 40 * 48; i += 128) { int n = i / 48, k = i % 48; w0p[i] = (k < 40) ? w0[n * 40 + k] : 0.f; }
        float* w1p = smf + W1P_OFF / 4;
        for (int i = tid; i < 24 * 48; i += 128) { int n = i / 48, k = i % 48; w1p[i] = (n < 20 && k < 40) ? w1[n * 40 + k] : 0.f; }
        float* w2p = smf + W2P_OFF / 4;
        for (int i = tid; i < 24 * 32; i += 128) { int n = i / 32, k = i % 32; w2p[i] = (n < 20 && k < 20) ? w2[n * 20 + k] : 0.f; }
        float* bb0 = smf + BIAS0_OFF / 4;
        for (int i = tid; i < 48; i += 128) bb0[i] = (i < 40) ? b0[i] : 0.f;
        float* bb1 = smf + BIAS1_OFF / 4;
        for (int i = tid; i < 24; i += 128) bb1[i] = (i < 20) ? b1[i] : 0.f;
        float* bb2 = smf + BIAS2_OFF / 4;
        for (int i = tid; i < 24; i += 128) bb2[i] = (i < 20) ? b2[i] : 0.f;
        float* fw = smf + FCW_OFF / 4;
        for (int i = tid; i < 400; i += 128) { int j = i / 20, k = i % 20; fw[k * 20 + j] = w3[i]; }
        for (int i = tid; i < 20;  i += 128) fw[400 + i] = b3[i];
        for (int i = tid; i < 240; i += 128) { int k = i / 12, j = i % 12; fw[420 + i] = (j < 10) ? w4[j * 20 + k] : 0.f; }
        for (int i = tid; i < 12;  i += 128) fw[660 + i] = (i < 10) ? b4[i] : 0.f;
        for (int i = tid; i < 12;  i += 128) fw[672 + i] = (i < 10) ? wf[i] : 0.f;
        if (tid == 0) { fw[684] = wscal[0]; fw[685] = bff[0]; }

        if (tid < 64) {
            float cs[7] = {0.f, 0.f, 0.f, 0.f, 0.f, 0.f, 0.f};
            int node = n0 + tid;
            if (node < N) {
                float c0a = nbc[node * 6 + 0], c0b = nbc[node * 6 + 1], c0c = nbc[node * 6 + 2];
                float c1a = nbc[node * 6 + 3], c1b = nbc[node * 6 + 4], c1c = nbc[node * 6 + 5];
                float w_ = wscal[0];
                float nb0 = c0a + c0b + c0c, nb1 = c1a + c1b + c1c;
                float nb0s = (nb0 < 1e-5f) ? 1e-5f : nb0;
                float nb1s = (nb1 < 1e-5f) ? 1e-5f : nb1;
                float h0 = (nb0 > 0.f) ? 1.f : 0.f;
                float h1 = (nb1 > 0.f) ? 1.f : 0.f;
                float inv0 = w_ / nb0s, inv1 = w_ / nb1s;
                cs[0] = 1.f - h0 * w_ - h1 * w_;
                cs[1] = c0a * inv0; cs[2] = c0b * inv0; cs[3] = c0c * inv0;
                cs[4] = c1a * inv1; cs[5] = c1b * inv1; cs[6] = c1c * inv1;
            }
            #pragma unroll
            for (int s = 0; s < 7; s++) smf[CS_OFF / 4 + tid * 7 + s] = cs[s];
        }

        // zero the k-pad columns (bytes 80..111) of both X buffers, once
        if (tid < 128) {
            int buf = tid >> 6, row = tid & 63;
            u32* pz = (u32*)(smem + (buf ? X1_OFF : X0_OFF) + row * 112 + 80);
            #pragma unroll
            for (int c = 0; c < 8; c++) pz[c] = 0u;
        }
    }
    __syncthreads();

    // ---- persistent B fragments in registers ----
    const int q = lane & 3;
    const int nn = lane >> 2;
    u32 w0f[15][2], w1f[9][2], w2f[6][2];
    {
        const float* w0p = smf + W0P_OFF / 4;
        #pragma unroll
        for (int f = 0; f < 3; f++)
            #pragma unroll
            for (int j = 0; j < 5; j++) {
                int k0 = f * 16 + 2 * q;
                const float* r = &w0p[(j * 8 + nn) * 48];
                CVT2(w0f[f * 5 + j][0], r[k0 + 0], r[k0 + 1]);
                CVT2(w0f[f * 5 + j][1], r[k0 + 8], r[k0 + 9]);
            }
        const float* w1p = smf + W1P_OFF / 4;
        #pragma unroll
        for (int f = 0; f < 3; f++)
            #pragma unroll
            for (int j = 0; j < 3; j++) {
                int k0 = f * 16 + 2 * q;
                const float* r = &w1p[(j * 8 + nn) * 48];
                CVT2(w1f[f * 3 + j][0], r[k0 + 0], r[k0 + 1]);
                CVT2(w1f[f * 3 + j][1], r[k0 + 8], r[k0 + 9]);
            }
        const float* w2p = smf + W2P_OFF / 4;
        #pragma unroll
        for (int f = 0; f < 2; f++)
            #pragma unroll
            for (int j = 0; j < 3; j++) {
                int k0 = f * 16 + 2 * q;
                const float* r = &w2p[(j * 8 + nn) * 32];
                CVT2(w2f[f * 3 + j][0], r[k0 + 0], r[k0 + 1]);
                CVT2(w2f[f * 3 + j][1], r[k0 + 8], r[k0 + 9]);
            }
    }

    const float* bb0 = smf + BIAS0_OFF / 4;
    const float* bb1 = smf + BIAS1_OFF / 4;
    const float* bb2 = smf + BIAS2_OFF / 4;
    const float* csa = smf + CS_OFF / 4;

    // per-thread staging offsets (precomputed once)
    int srow[5], soff[5], goff[5];
    #pragma unroll
    for (int it = 0; it < 5; it++) {
        int i = it * 128 + tid;
        int row = i / 10, qq = i % 10;
        srow[it] = row;
        soff[it] = row * 112 + qq * 8;   // bytes into X tile
        goff[it] = row * 10 + qq;        // quads into feature tile
    }

    // ldmatrix lane addressing
    const int lg = lane >> 3, lr = lane & 7;
    const int arow = warp * 16 + (lg & 1) * 8 + lr;
    const int acolb = (lg >> 1) * 8;

    const float wt = (tid < nvalid) ? wts[n0 + tid] : 0.f;
    const float* fw = smf + FCW_OFF / 4;

    #pragma unroll 1
    for (int bq = 0; bq < B; bq++) {
        const float4* fbB = (const float4*)feat + ((size_t)bq * N + n0) * 70;

        // preload tile 0
        float4 xv[5];
        #pragma unroll
        for (int it = 0; it < 5; it++)
            if (srow[it] < vrows) xv[it] = fbB[goff[it]];

        #pragma unroll 1
        for (int t = 0; t < 7; t++) {
            const u32 xbase = sb + ((t & 1) ? X1_OFF : X0_OFF);

            // convert + STS current tile
            #pragma unroll
            for (int it = 0; it < 5; it++) {
                u32 p0, p1;
                CVT2(p0, xv[it].x, xv[it].y);
                CVT2(p1, xv[it].z, xv[it].w);
                asm volatile("st.shared.v2.b32 [%0], {%1, %2};"
                             :: "r"(xbase + (u32)soff[it]), "r"(p0), "r"(p1) : "memory");
            }
            // issue loads for next tile (hidden under mma below)
            if (t < 6) {
                #pragma unroll
                for (int it = 0; it < 5; it++)
                    if ((t + 1) * 64 + srow[it] < vrows) xv[it] = fbB[(t + 1) * 640 + goff[it]];
            }
            __syncthreads();

            // ---- per-warp slab: 16 rows, full fc0 chain in registers ----
            u32 a0f[3][4];
            #pragma unroll
            for (int f = 0; f < 3; f++)
                ldm4(a0f[f], xbase + (u32)(arow * 112 + (f * 16 + acolb) * 2));

            float d[5][4];
            #pragma unroll
            for (int j = 0; j < 5; j++) { d[j][0] = 0.f; d[j][1] = 0.f; d[j][2] = 0.f; d[j][3] = 0.f; }
            #pragma unroll
            for (int f = 0; f < 3; f++)
                #pragma unroll
                for (int j = 0; j < 5; j++)
                    mma16816(d[j], a0f[f], w0f[f * 5 + j]);

            u32 a1f[3][4];
            #pragma unroll
            for (int j = 0; j < 5; j++) {
                int c0 = j * 8 + 2 * q;
                float bl = bb0[c0], bh = bb0[c0 + 1];
                float t0 = fast_tanh(d[j][0] + bl);
                float t1 = fast_tanh(d[j][1] + bh);
                float t2 = fast_tanh(d[j][2] + bl);
                float t3 = fast_tanh(d[j][3] + bh);
                u32 plo, phi;
                CVT2(plo, t0, t1);
                CVT2(phi, t2, t3);
                a1f[j >> 1][(j & 1) ? 2 : 0] = plo;
                a1f[j >> 1][(j & 1) ? 3 : 1] = phi;
            }
            a1f[2][2] = 0u; a1f[2][3] = 0u;

            float e[3][4];
            #pragma unroll
            for (int j = 0; j < 3; j++) { e[j][0] = 0.f; e[j][1] = 0.f; e[j][2] = 0.f; e[j][3] = 0.f; }
            #pragma unroll
            for (int f = 0; f < 3; f++)
                #pragma unroll
                for (int j = 0; j < 3; j++)
                    mma16816(e[j], a1f[f], w1f[f * 3 + j]);

            u32 a2f[2][4];
            #pragma unroll
            for (int j = 0; j < 3; j++) {
                int c0 = j * 8 + 2 * q;
                float bl = bb1[c0], bh = bb1[c0 + 1];
                float t0 = (c0 < 20)     ? fast_tanh(e[j][0] + bl) : 0.f;
                float t1 = (c0 + 1 < 20) ? fast_tanh(e[j][1] + bh) : 0.f;
                float t2 = (c0 < 20)     ? fast_tanh(e[j][2] + bl) : 0.f;
                float t3 = (c0 + 1 < 20) ? fast_tanh(e[j][3] + bh) : 0.f;
                u32 plo, phi;
                CVT2(plo, t0, t1);
                CVT2(phi, t2, t3);
                a2f[j >> 1][(j & 1) ? 2 : 0] = plo;
                a2f[j >> 1][(j & 1) ? 3 : 1] = phi;
            }
            a2f[1][2] = 0u; a2f[1][3] = 0u;

            float o[3][4];
            #pragma unroll
            for (int j = 0; j < 3; j++) { o[j][0] = 0.f; o[j][1] = 0.f; o[j][2] = 0.f; o[j][3] = 0.f; }
            #pragma unroll
            for (int f = 0; f < 2; f++)
                #pragma unroll
                for (int j = 0; j < 3; j++)
                    mma16816(o[j], a2f[f], w2f[f * 3 + j]);

            int r0 = t * 64 + warp * 16 + (lane >> 2);
            int r1 = r0 + 8;
            float cs0 = csa[r0], cs1 = csa[r1];
            #pragma unroll
            for (int j = 0; j < 3; j++) {
                int c0 = j * 8 + 2 * q;
                if (c0 < 20) {
                    float bl = bb2[c0], bh = bb2[c0 + 1];
                    float v0 = cs0 * fast_tanh(o[j][0] + bl);
                    float v1 = cs0 * fast_tanh(o[j][1] + bh);
                    float v2 = cs1 * fast_tanh(o[j][2] + bl);
                    float v3 = cs1 * fast_tanh(o[j][3] + bh);
                    *(float2*)(smem + P_OFF + (u32)(r0 * 80 + c0 * 4)) = make_float2(v0, v1);
                    *(float2*)(smem + P_OFF + (u32)(r1 * 80 + c0 * 4)) = make_float2(v2, v3);
                }
            }
        }
        __syncthreads();

        // ---- tail: gather P, fc1, head (threads 0..nvalid) ----
        float contrib = 0.f;
        if (tid < nvalid) {
            float m[20];
            #pragma unroll
            for (int d2 = 0; d2 < 20; d2++) m[d2] = 0.f;
            #pragma unroll
            for (int s = 0; s < 7; s++) {
                const float4* pr = (const float4*)(smem + P_OFF + (u32)((tid * 7 + s) * 80));
                #pragma unroll
                for (int c = 0; c < 5; c++) {
                    float4 vv = pr[c];
                    m[4 * c + 0] += vv.x; m[4 * c + 1] += vv.y;
                    m[4 * c + 2] += vv.z; m[4 * c + 3] += vv.w;
                }
            }

            u64 p[10];
            const u64* bp3 = (const u64*)&fw[400];
            #pragma unroll
            for (int j = 0; j < 10; j++) p[j] = bp3[j];
            #pragma unroll
            for (int k = 0; k < 20; k++) {
                u64 xx = pk2(m[k]);
                const ulonglong2* wr = (const ulonglong2*)&fw[k * 20];
                #pragma unroll
                for (int j2 = 0; j2 < 5; j2++) {
                    ulonglong2 wv = wr[j2];
                    p[2 * j2 + 0] = ffma2(xx, wv.x, p[2 * j2 + 0]);
                    p[2 * j2 + 1] = ffma2(xx, wv.y, p[2 * j2 + 1]);
                }
            }
            float pt[20];
            #pragma unroll
            for (int j = 0; j < 10; j++) {
                float a, c; upk(p[j], a, c);
                pt[2 * j + 0] = fast_tanh(a);
                pt[2 * j + 1] = fast_tanh(c);
            }

            u64 qq[6];
            const u64* bp4 = (const u64*)&fw[660];
            #pragma unroll
            for (int j = 0; j < 6; j++) qq[j] = bp4[j];
            #pragma unroll
            for (int k = 0; k < 20; k++) {
                u64 xx = pk2(pt[k]);
                const ulonglong2* wr = (const ulonglong2*)&fw[420 + k * 12];
                #pragma unroll
                for (int j2 = 0; j2 < 3; j2++) {
                    ulonglong2 wv = wr[j2];
                    qq[2 * j2 + 0] = ffma2(xx, wv.x, qq[2 * j2 + 0]);
                    qq[2 * j2 + 1] = ffma2(xx, wv.y, qq[2 * j2 + 1]);
                }
            }

            float ev = fw[685];
            #pragma unroll
            for (int j = 0; j < 6; j++) {
                float a, c; upk(qq[j], a, c);
                ev += fast_tanh(a) * fw[672 + 2 * j + 0];
                ev += fast_tanh(c) * fw[672 + 2 * j + 1];
            }
            contrib = wt * ev;
        }

        float* red = smf + RED_OFF / 4;
        red[tid] = contrib;
        __syncthreads();
        #pragma unroll
        for (int o2 = 64; o2 > 0; o2 >>= 1) {
            if (tid < o2) red[tid] += red[tid + o2];
            __syncthreads();
        }
        if (tid == 0) atomicAdd(&out[bq], SIGMA_C * red[0]);
        __syncthreads();
    }
}

extern "C" void kernel_launch(void* const* d_in, const int* in_sizes, int n_in,
                              void* d_out, int out_size)
{
    const float* feat  = (const float*)d_in[0];
    const float* nbc   = (const float*)d_in[1];
    const float* wts   = (const float*)d_in[2];
    const float* wscal = (const float*)d_in[3];
    const float* w0 = (const float*)d_in[4];
    const float* b0 = (const float*)d_in[5];
    const float* w1 = (const float*)d_in[6];
    const float* b1 = (const float*)d_in[7];
    const float* w2 = (const float*)d_in[8];
    const float* b2 = (const float*)d_in[9];
    const float* w3 = (const float*)d_in[10];
    const float* b3 = (const float*)d_in[11];
    const float* w4 = (const float*)d_in[12];
    const float* b4 = (const float*)d_in[13];
    const float* wf = (const float*)d_in[14];
    const float* bff = (const float*)d_in[15];
    float* out = (float*)d_out;

    const int N = in_sizes[2];
    const int B = out_size;

    cudaFuncSetAttribute(gnn_mma_kernel, cudaFuncAttributeMaxDynamicSharedMemorySize, SMEM_BYTES);

    init_out_kernel<<<1, 32>>>(out, B);
    dim3 grid((N + 63) / 64);
    gnn_mma_kernel<<<grid, 128, SMEM_BYTES>>>(feat, nbc, wts, wscal,
                                              w0, b0, w1, b1, w2, b2,
                                              w3, b3, w4, b4, wf, bff,
                                              out, N, B);
}